// round 6
// baseline (speedup 1.0000x reference)
#include <cuda_runtime.h>
#include <cuda_bf16.h>
#include <math.h>
#include <stdint.h>

// Problem constants
#define BB 8
#define NN 2048
#define CC 1024
#define HH 16
#define DD 64
#define MM (BB*NN)        // 16384 rows
#define HALFC (CC/2)
#define NSPLIT 8

// Scratch (device globals: allocation-free per harness rules)
__device__ float g_Q[MM*CC];
__device__ float g_K[MM*CC];
__device__ float g_V[MM*CC];
__device__ float g_O[MM*CC];
__device__ float g_kvp[NSPLIT*BB*HH*DD*DD];
__device__ float g_kmp[NSPLIT*BB*HH*DD];
__device__ float g_kv[BB*HH*DD*DD];
__device__ float g_km[BB*HH*DD];
__device__ float g_invfreq[HALFC];
__device__ float g_cos[NN*HALFC];
__device__ float g_sin[NN*HALFC];

// bf16 split operands
__device__ __nv_bfloat16 g_Ahi[MM*CC];
__device__ __nv_bfloat16 g_Alo[MM*CC];
__device__ __nv_bfloat16 g_Whi[3][CC*CC];
__device__ __nv_bfloat16 g_Wlo[3][CC*CC];

// ---------------------------------------------------------------------------
__global__ void init_invfreq_kernel() {
    int j = threadIdx.x;
    if (j < HALFC)
        g_invfreq[j] = (float)(1.0 / pow(10000.0, (double)(2 * j) / (double)CC));
}

// Precompute rope tables: cos/sin(n * invfreq[j]) for all n, j
__global__ __launch_bounds__(512) void init_rope_kernel() {
    int n = blockIdx.x;
    int j = threadIdx.x;
    float ang = (float)n * g_invfreq[j];
    float sv, cv;
    sincosf(ang, &sv, &cv);
    g_cos[n * HALFC + j] = cv;
    g_sin[n * HALFC + j] = sv;
}

// ---------------------------------------------------------------------------
// Split fp32 -> bf16 hi/lo
__global__ __launch_bounds__(256) void split_x_kernel(const float* __restrict__ x) {
    size_t i = (size_t)blockIdx.x * 256 + threadIdx.x;   // float4 index
    float4 v = *(const float4*)(x + i * 4);
    float f[4] = {v.x, v.y, v.z, v.w};
    union { __nv_bfloat16 h[4]; uint2 u; } H, L;
    #pragma unroll
    for (int k = 0; k < 4; k++) {
        __nv_bfloat16 hh = __float2bfloat16(f[k]);
        H.h[k] = hh;
        L.h[k] = __float2bfloat16(f[k] - __bfloat162float(hh));
    }
    *(uint2*)&g_Ahi[i * 4] = H.u;
    *(uint2*)&g_Alo[i * 4] = L.u;
}

__global__ __launch_bounds__(256) void split_w_kernel(
    const float* __restrict__ W0, const float* __restrict__ W1,
    const float* __restrict__ W2)
{
    int idx = blockIdx.y;
    const float* __restrict__ W = (idx == 0) ? W0 : (idx == 1) ? W1 : W2;
    size_t i = (size_t)blockIdx.x * 256 + threadIdx.x;
    float4 v = *(const float4*)(W + i * 4);
    float f[4] = {v.x, v.y, v.z, v.w};
    union { __nv_bfloat16 h[4]; uint2 u; } H, L;
    #pragma unroll
    for (int k = 0; k < 4; k++) {
        __nv_bfloat16 hh = __float2bfloat16(f[k]);
        H.h[k] = hh;
        L.h[k] = __float2bfloat16(f[k] - __bfloat162float(hh));
    }
    *(uint2*)&g_Whi[idx][i * 4] = H.u;
    *(uint2*)&g_Wlo[idx][i * 4] = L.u;
}

// ---------------------------------------------------------------------------
// Tensor-core GEMM (HMMA mma.sync): Y[m,n] = sum_k A[m,k]*W[n,k] + bias[n]
// bf16x3 split, fp32 acc. Tile 256x128, BK=64, 3-stage cp.async pipeline,
// 512 threads (4x4 warps, warp tile 64x32). blockIdx.z selects Q/K/V.
#define SA 72                          // padded smem row stride (bf16): 144B
#define ASZ (256 * SA * 2)             // A stage bytes = 36864
#define WSZ (128 * SA * 2)             // W stage bytes = 18432
#define STGSZ (ASZ + WSZ)              // 55296
#define GEMM_SMEM (3 * STGSZ)          // 165888
#define NIT 48                         // 3 split passes x (1024/64)

__device__ __forceinline__ void ldsm4(unsigned* r, uint32_t addr) {
    asm volatile("ldmatrix.sync.aligned.m8n8.x4.shared.b16 {%0,%1,%2,%3},[%4];\n"
                 : "=r"(r[0]), "=r"(r[1]), "=r"(r[2]), "=r"(r[3]) : "r"(addr));
}
__device__ __forceinline__ void mma16816(float* d, const unsigned* a, const unsigned* b) {
    asm volatile("mma.sync.aligned.m16n8k16.row.col.f32.bf16.bf16.f32 "
                 "{%0,%1,%2,%3},{%4,%5,%6,%7},{%8,%9},{%0,%1,%2,%3};\n"
                 : "+f"(d[0]), "+f"(d[1]), "+f"(d[2]), "+f"(d[3])
                 : "r"(a[0]), "r"(a[1]), "r"(a[2]), "r"(a[3]), "r"(b[0]), "r"(b[1]));
}

__global__ __launch_bounds__(512, 1) void gemm_mma_kernel(
    const float* __restrict__ bq, const float* __restrict__ bk,
    const float* __restrict__ bv)
{
    extern __shared__ __nv_bfloat16 sm[];
    const int which = blockIdx.z;
    const float* __restrict__ bias = (which == 0) ? bq : (which == 1) ? bk : bv;
    float* __restrict__ Y = (which == 0) ? g_Q : (which == 1) ? g_K : g_V;
    const bool gel = (which < 2);
    const __nv_bfloat16* __restrict__ Wh = g_Whi[which];
    const __nv_bfloat16* __restrict__ Wl = g_Wlo[which];

    const int t = threadIdx.x;
    const int lane = t & 31, warp = t >> 5;
    const int wm = warp >> 2, wn = warp & 3;     // 4x4 warps; warp tile 64m x 32n
    const int m0 = blockIdx.y * 256, n0 = blockIdx.x * 128;

    const uint32_t sBase = (uint32_t)__cvta_generic_to_shared(sm);

    float acc[4][4][4];
    #pragma unroll
    for (int mt = 0; mt < 4; mt++)
        #pragma unroll
        for (int nt = 0; nt < 4; nt++)
            #pragma unroll
            for (int r = 0; r < 4; r++) acc[mt][nt][r] = 0.f;

    // it: 0..47.  phase = it/16: 0 Ahi*Whi, 1 Ahi*Wlo, 2 Alo*Whi. kk = (it%16)*64.
    auto prefetch = [&](int it, int stg) {
        int ph = it >> 4;
        const __nv_bfloat16* Ap = (ph < 2) ? g_Ahi : g_Alo;
        const __nv_bfloat16* Wp = (ph == 1) ? Wl : Wh;
        int kk = (it & 15) << 6;
        uint32_t sA = sBase + stg * STGSZ;
        uint32_t sW = sA + ASZ;
        #pragma unroll
        for (int i = 0; i < 6; i++) {
            int c = t + i * 512;                 // 0..3071 16B chunks
            int isW = c >> 11;                   // A: 2048 chunks, W: 1024
            int cc = isW ? (c - 2048) : c;
            int row = cc >> 3, seg = cc & 7;
            const __nv_bfloat16* gp = isW
                ? Wp + (size_t)(n0 + row) * CC + kk + seg * 8
                : Ap + (size_t)(m0 + row) * CC + kk + seg * 8;
            uint32_t sp = (isW ? sW : sA) + (row * SA + seg * 8) * 2;
            asm volatile("cp.async.cg.shared.global [%0],[%1],16;\n" :: "r"(sp), "l"(gp));
        }
        asm volatile("cp.async.commit_group;\n");
    };

    const int aRow = lane & 15, aCol = (lane >> 4) << 3;
    const int bRow = (lane & 7) + ((lane >> 4) << 3), bCol = ((lane >> 3) & 1) << 3;

    prefetch(0, 0);
    prefetch(1, 1);

    #pragma unroll 1
    for (int it = 0; it < NIT; ++it) {
        if (it < NIT - 1) asm volatile("cp.async.wait_group 1;\n");
        else              asm volatile("cp.async.wait_group 0;\n");
        __syncthreads();
        if (it + 2 < NIT) prefetch(it + 2, (it + 2) % 3);

        const uint32_t sA = sBase + (it % 3) * STGSZ;
        const uint32_t sW = sA + ASZ;
        #pragma unroll
        for (int ks = 0; ks < 4; ++ks) {
            unsigned a[4][4], bf[2][4];
            #pragma unroll
            for (int mt = 0; mt < 4; ++mt)
                ldsm4(a[mt], sA + ((wm * 64 + mt * 16 + aRow) * SA + ks * 16 + aCol) * 2);
            #pragma unroll
            for (int nb = 0; nb < 2; ++nb)
                ldsm4(bf[nb], sW + ((wn * 32 + nb * 16 + bRow) * SA + ks * 16 + bCol) * 2);
            #pragma unroll
            for (int mt = 0; mt < 4; ++mt)
                #pragma unroll
                for (int nt = 0; nt < 4; ++nt)
                    mma16816(acc[mt][nt], a[mt], &bf[nt >> 1][(nt & 1) * 2]);
        }
    }

    // Epilogue: bias (+ exact GELU + 0.21 for Q/K)
    const int gid = lane >> 2, tid2 = lane & 3;
    #pragma unroll
    for (int mt = 0; mt < 4; ++mt) {
        int r0 = m0 + wm * 64 + mt * 16 + gid;
        #pragma unroll
        for (int nt = 0; nt < 4; ++nt) {
            int col = n0 + wn * 32 + nt * 8 + tid2 * 2;
            float b0 = __ldg(&bias[col]), b1 = __ldg(&bias[col + 1]);
            float y0 = acc[mt][nt][0] + b0, y1 = acc[mt][nt][1] + b1;
            float y2 = acc[mt][nt][2] + b0, y3 = acc[mt][nt][3] + b1;
            if (gel) {
                y0 = 0.5f * y0 * (1.f + erff(y0 * 0.7071067811865476f)) + 0.21f;
                y1 = 0.5f * y1 * (1.f + erff(y1 * 0.7071067811865476f)) + 0.21f;
                y2 = 0.5f * y2 * (1.f + erff(y2 * 0.7071067811865476f)) + 0.21f;
                y3 = 0.5f * y3 * (1.f + erff(y3 * 0.7071067811865476f)) + 0.21f;
            }
            *(float2*)&Y[(size_t)r0 * CC + col] = make_float2(y0, y1);
            *(float2*)&Y[(size_t)(r0 + 8) * CC + col] = make_float2(y2, y3);
        }
    }
}

// ---------------------------------------------------------------------------
// kv partial: per (b,h,split) accumulate  sum_n rope(k)[n,d]*v[n,e]  and sum_n k[n,d]
__global__ __launch_bounds__(256) void kv_partial_kernel() {
    int bh = blockIdx.x;
    int sp = blockIdx.y;
    int b = bh >> 4, h = bh & 15;
    int t = threadIdx.x;

    __shared__ float ks[32 * 64];
    __shared__ float krs[32 * 64];
    __shared__ float vs[32 * 64];

    int tx = t & 15, ty = t >> 4;
    float acc[4][4];
    #pragma unroll
    for (int i = 0; i < 4; i++)
        #pragma unroll
        for (int j = 0; j < 4; j++) acc[i][j] = 0.f;
    float ksum = 0.f;

    for (int ch = 0; ch < 8; ch++) {
        int n0 = sp * 256 + ch * 32;
        #pragma unroll
        for (int ld = 0; ld < 2; ld++) {
            int idx = t + ld * 256;
            int r = idx >> 4, c4 = idx & 15;
            size_t gofs = (size_t)(b * NN + n0 + r) * CC + h * DD + c4 * 4;
            *(float4*)&ks[r * 64 + c4 * 4] = *(const float4*)&g_K[gofs];
            *(float4*)&vs[r * 64 + c4 * 4] = *(const float4*)&g_V[gofs];
        }
        __syncthreads();
        #pragma unroll
        for (int pp = 0; pp < 4; pp++) {
            int p = t + pp * 256;
            int r = p >> 5, jj = p & 31;
            float a  = ks[r * 64 + 2 * jj];
            float bv = ks[r * 64 + 2 * jj + 1];
            int tofs = (n0 + r) * HALFC + h * 32 + jj;
            float cv = g_cos[tofs], sv = g_sin[tofs];
            krs[r * 64 + 2 * jj]     = a * cv - bv * sv;
            krs[r * 64 + 2 * jj + 1] = bv * cv + a * sv;
        }
        if (t < 64) {
            #pragma unroll
            for (int r = 0; r < 32; r++) ksum += ks[r * 64 + t];
        }
        __syncthreads();
        #pragma unroll
        for (int nn = 0; nn < 32; nn++) {
            float4 kr4 = *(float4*)&krs[nn * 64 + ty * 4];
            float4 vv4 = *(float4*)&vs[nn * 64 + tx * 4];
            float kr[4] = {kr4.x, kr4.y, kr4.z, kr4.w};
            float vv[4] = {vv4.x, vv4.y, vv4.z, vv4.w};
            #pragma unroll
            for (int i = 0; i < 4; i++)
                #pragma unroll
                for (int j = 0; j < 4; j++)
                    acc[i][j] += kr[i] * vv[j];
        }
        __syncthreads();
    }

    float* kvp = &g_kvp[((size_t)sp * (BB * HH) + bh) * (DD * DD)];
    #pragma unroll
    for (int i = 0; i < 4; i++)
        #pragma unroll
        for (int j = 0; j < 4; j++)
            kvp[(ty * 4 + i) * DD + tx * 4 + j] = acc[i][j];
    if (t < 64)
        g_kmp[((size_t)sp * (BB * HH) + bh) * DD + t] = ksum;
}

__global__ __launch_bounds__(256) void kv_reduce_kernel() {
    int bh = blockIdx.x;
    int t = threadIdx.x;
    const float inv = 1.f / (float)NN;
    for (int i = t; i < DD * DD; i += 256) {
        float s = 0.f;
        #pragma unroll
        for (int sp = 0; sp < NSPLIT; sp++)
            s += g_kvp[((size_t)sp * (BB * HH) + bh) * (DD * DD) + i];
        g_kv[(size_t)bh * (DD * DD) + i] = s * inv;
    }
    if (t < DD) {
        float s = 0.f;
        #pragma unroll
        for (int sp = 0; sp < NSPLIT; sp++)
            s += g_kmp[((size_t)sp * (BB * HH) + bh) * DD + t];
        g_km[(size_t)bh * DD + t] = s * inv;
    }
}

// ---------------------------------------------------------------------------
__global__ __launch_bounds__(256) void out_kernel() {
    int bh = blockIdx.x;
    int b = bh >> 4, h = bh & 15;
    int n0 = blockIdx.y * 32;
    int t = threadIdx.x;

    __shared__ float kvs[DD * DD];
    __shared__ float kms[DD];
    __shared__ float qs[16 * 64];
    __shared__ float qrs[16 * 64];

    #pragma unroll
    for (int ld = 0; ld < 4; ld++) {
        int i4 = t + ld * 256;
        *(float4*)&kvs[i4 * 4] = *(const float4*)&g_kv[(size_t)bh * (DD * DD) + i4 * 4];
    }
    if (t < DD) kms[t] = g_km[(size_t)bh * DD + t];
    __syncthreads();

    int tg = t & 15, rr = t >> 4;
    for (int ig = 0; ig < 2; ig++) {
        int n = n0 + ig * 16 + rr;
        *(float4*)&qs[rr * 64 + tg * 4] =
            *(const float4*)&g_Q[(size_t)(b * NN + n) * CC + h * DD + tg * 4];
        __syncthreads();
        #pragma unroll
        for (int pp = 0; pp < 2; pp++) {
            int p = t + pp * 256;
            int r = p >> 5, jj = p & 31;
            float a  = qs[r * 64 + 2 * jj];
            float bv = qs[r * 64 + 2 * jj + 1];
            int tofs = (n0 + ig * 16 + r) * HALFC + h * 32 + jj;
            float cv = g_cos[tofs], sv = g_sin[tofs];
            qrs[r * 64 + 2 * jj]     = a * cv - bv * sv;
            qrs[r * 64 + 2 * jj + 1] = bv * cv + a * sv;
        }
        float zacc = 0.f;
        #pragma unroll
        for (int d = 0; d < DD; d++) zacc += qs[rr * 64 + d] * kms[d];
        float z = 1.f / (zacc + 1e-6f);
        __syncthreads();
        float4 o = {0.f, 0.f, 0.f, 0.f};
        #pragma unroll
        for (int d = 0; d < DD; d++) {
            float qv = qrs[rr * 64 + d];
            float4 kvv = *(float4*)&kvs[d * 64 + tg * 4];
            o.x += qv * kvv.x; o.y += qv * kvv.y;
            o.z += qv * kvv.z; o.w += qv * kvv.w;
        }
        o.x *= z; o.y *= z; o.z *= z; o.w *= z;
        *(float4*)&g_O[(size_t)(b * NN + n) * CC + h * DD + tg * 4] = o;
        __syncthreads();
    }
}

// ---------------------------------------------------------------------------
__global__ __launch_bounds__(256) void ln_kernel(
    const float* __restrict__ x, const float* __restrict__ gamma,
    const float* __restrict__ beta, float* __restrict__ out)
{
    int row = blockIdx.x;
    int t = threadIdx.x;
    float4 a  = *(const float4*)&g_O[(size_t)row * CC + t * 4];
    float4 xv = *(const float4*)&x[(size_t)row * CC + t * 4];
    float4 r;
    r.x = a.x + xv.x; r.y = a.y + xv.y; r.z = a.z + xv.z; r.w = a.w + xv.w;
    float s  = r.x + r.y + r.z + r.w;
    float sq = r.x * r.x + r.y * r.y + r.z * r.z + r.w * r.w;
    #pragma unroll
    for (int off = 16; off; off >>= 1) {
        s  += __shfl_xor_sync(0xffffffffu, s, off);
        sq += __shfl_xor_sync(0xffffffffu, sq, off);
    }
    __shared__ float ss[8], ssq[8];
    __shared__ float mean_s, rstd_s;
    int w = t >> 5, lane = t & 31;
    if (lane == 0) { ss[w] = s; ssq[w] = sq; }
    __syncthreads();
    if (t == 0) {
        float S = 0.f, SQ = 0.f;
        #pragma unroll
        for (int i = 0; i < 8; i++) { S += ss[i]; SQ += ssq[i]; }
        float mean = S * (1.f / (float)CC);
        float var  = SQ * (1.f / (float)CC) - mean * mean;
        mean_s = mean;
        rstd_s = rsqrtf(var + 1e-12f);
    }
    __syncthreads();
    float mean = mean_s, rstd = rstd_s;
    float4 g  = *(const float4*)&gamma[t * 4];
    float4 be = *(const float4*)&beta[t * 4];
    float4 o;
    o.x = (r.x - mean) * rstd * g.x + be.x;
    o.y = (r.y - mean) * rstd * g.y + be.y;
    o.z = (r.z - mean) * rstd * g.z + be.z;
    o.w = (r.w - mean) * rstd * g.w + be.w;
    *(float4*)&out[(size_t)row * CC + t * 4] = o;
}

// ---------------------------------------------------------------------------
extern "C" void kernel_launch(void* const* d_in, const int* in_sizes, int n_in,
                              void* d_out, int out_size) {
    const float* x     = (const float*)d_in[0];
    const float* Wq    = (const float*)d_in[1];
    const float* bq    = (const float*)d_in[2];
    const float* Wk    = (const float*)d_in[3];
    const float* bk    = (const float*)d_in[4];
    const float* Wv    = (const float*)d_in[5];
    const float* bv    = (const float*)d_in[6];
    const float* gamma = (const float*)d_in[7];
    const float* beta  = (const float*)d_in[8];
    float* out = (float*)d_out;

    init_invfreq_kernel<<<1, 512>>>();
    init_rope_kernel<<<NN, 512>>>();

    split_x_kernel<<<MM * CC / 1024, 256>>>(x);
    split_w_kernel<<<dim3(CC * CC / 1024, 3), 256>>>(Wq, Wk, Wv);

    cudaFuncSetAttribute(gemm_mma_kernel,
                         cudaFuncAttributeMaxDynamicSharedMemorySize, GEMM_SMEM);
    dim3 ggrid(CC / 128, MM / 256, 3);               // (8, 64, 3)
    gemm_mma_kernel<<<ggrid, 512, GEMM_SMEM>>>(bq, bk, bv);

    kv_partial_kernel<<<dim3(BB * HH, NSPLIT), 256>>>();
    kv_reduce_kernel<<<BB * HH, 256>>>();
    out_kernel<<<dim3(BB * HH, NN / 32), 256>>>();
    ln_kernel<<<MM, 256>>>(x, gamma, beta, out);
}

// round 7
// speedup vs baseline: 1.9389x; 1.9389x over previous
#include <cuda_runtime.h>
#include <cuda_bf16.h>
#include <math.h>
#include <stdint.h>

// Problem constants
#define BB 8
#define NN 2048
#define CC 1024
#define HH 16
#define DD 64
#define MM (BB*NN)        // 16384 rows
#define HALFC (CC/2)
#define NSPLIT 8

// Scratch (device globals: allocation-free per harness rules)
__device__ float g_Q[MM*CC];
__device__ float g_K[MM*CC];
__device__ float g_V[MM*CC];
__device__ float g_O[MM*CC];
__device__ float g_kvp[NSPLIT*BB*HH*DD*DD];
__device__ float g_kmp[NSPLIT*BB*HH*DD];
__device__ float g_kv[BB*HH*DD*DD];
__device__ float g_km[BB*HH*DD];
__device__ float g_invfreq[HALFC];
__device__ float g_cos[NN*HALFC];
__device__ float g_sin[NN*HALFC];

// bf16 operands
__device__ __nv_bfloat16 g_Abf[MM*CC];
__device__ __nv_bfloat16 g_Wbf[3][CC*CC];

// ---------------------------------------------------------------------------
__global__ void init_invfreq_kernel() {
    int j = threadIdx.x;
    if (j < HALFC)
        g_invfreq[j] = (float)(1.0 / pow(10000.0, (double)(2 * j) / (double)CC));
}

// Precompute rope tables: cos/sin(n * invfreq[j]) for all n, j
__global__ __launch_bounds__(512) void init_rope_kernel() {
    int n = blockIdx.x;
    int j = threadIdx.x;
    float ang = (float)n * g_invfreq[j];
    float sv, cv;
    sincosf(ang, &sv, &cv);
    g_cos[n * HALFC + j] = cv;
    g_sin[n * HALFC + j] = sv;
}

// ---------------------------------------------------------------------------
// fp32 -> bf16 conversion
__global__ __launch_bounds__(256) void conv_x_kernel(const float* __restrict__ x) {
    size_t i = (size_t)blockIdx.x * 256 + threadIdx.x;   // float4 index
    float4 v = *(const float4*)(x + i * 4);
    union { __nv_bfloat16 h[4]; uint2 u; } H;
    H.h[0] = __float2bfloat16(v.x); H.h[1] = __float2bfloat16(v.y);
    H.h[2] = __float2bfloat16(v.z); H.h[3] = __float2bfloat16(v.w);
    *(uint2*)&g_Abf[i * 4] = H.u;
}

__global__ __launch_bounds__(256) void conv_w_kernel(
    const float* __restrict__ W0, const float* __restrict__ W1,
    const float* __restrict__ W2)
{
    int idx = blockIdx.y;
    const float* __restrict__ W = (idx == 0) ? W0 : (idx == 1) ? W1 : W2;
    size_t i = (size_t)blockIdx.x * 256 + threadIdx.x;
    float4 v = *(const float4*)(W + i * 4);
    union { __nv_bfloat16 h[4]; uint2 u; } H;
    H.h[0] = __float2bfloat16(v.x); H.h[1] = __float2bfloat16(v.y);
    H.h[2] = __float2bfloat16(v.z); H.h[3] = __float2bfloat16(v.w);
    *(uint2*)&g_Wbf[idx][i * 4] = H.u;
}

// ---------------------------------------------------------------------------
// Tensor-core GEMM (HMMA mma.sync): Y[m,n] = sum_k A[m,k]*W[n,k] + bias[n]
// Single-pass bf16, fp32 acc. Tile 128x128, BK=64, 3-stage cp.async pipeline.
// blockIdx.z selects Q/K/V.
#define SA 72                      // padded smem row stride (bf16): 144B, conflict-free
#define OPSZ (128 * SA * 2)        // bytes per operand per stage = 18432
#define STGSZ (2 * OPSZ)           // bytes per stage (A+W)       = 36864
#define GEMM_SMEM (3 * STGSZ)      // 110592
#define NIT 16                     // 1024 / 64

__device__ __forceinline__ void ldsm4(unsigned* r, uint32_t addr) {
    asm volatile("ldmatrix.sync.aligned.m8n8.x4.shared.b16 {%0,%1,%2,%3},[%4];\n"
                 : "=r"(r[0]), "=r"(r[1]), "=r"(r[2]), "=r"(r[3]) : "r"(addr));
}
__device__ __forceinline__ void mma16816(float* d, const unsigned* a, const unsigned* b) {
    asm volatile("mma.sync.aligned.m16n8k16.row.col.f32.bf16.bf16.f32 "
                 "{%0,%1,%2,%3},{%4,%5,%6,%7},{%8,%9},{%0,%1,%2,%3};\n"
                 : "+f"(d[0]), "+f"(d[1]), "+f"(d[2]), "+f"(d[3])
                 : "r"(a[0]), "r"(a[1]), "r"(a[2]), "r"(a[3]), "r"(b[0]), "r"(b[1]));
}

__global__ __launch_bounds__(256, 2) void gemm_mma_kernel(
    const float* __restrict__ bq, const float* __restrict__ bk,
    const float* __restrict__ bv)
{
    extern __shared__ __nv_bfloat16 sm[];
    const int which = blockIdx.z;
    const float* __restrict__ bias = (which == 0) ? bq : (which == 1) ? bk : bv;
    float* __restrict__ Y = (which == 0) ? g_Q : (which == 1) ? g_K : g_V;
    const bool gel = (which < 2);
    const __nv_bfloat16* __restrict__ Wp = g_Wbf[which];

    const int t = threadIdx.x;
    const int lane = t & 31, warp = t >> 5;
    const int wm = warp & 3, wn = warp >> 2;     // 4 x 2 warp grid, warp tile 32x64
    const int m0 = blockIdx.y * 128, n0 = blockIdx.x * 128;

    const uint32_t sBase = (uint32_t)__cvta_generic_to_shared(sm);

    float acc[2][8][4];
    #pragma unroll
    for (int mt = 0; mt < 2; mt++)
        #pragma unroll
        for (int j = 0; j < 8; j++)
            #pragma unroll
            for (int r = 0; r < 4; r++) acc[mt][j][r] = 0.f;

    auto prefetch = [&](int it, int stg) {
        int kk = it << 6;
        uint32_t sA = sBase + stg * STGSZ;
        uint32_t sW = sA + OPSZ;
        #pragma unroll
        for (int i = 0; i < 8; i++) {
            int c = t + i * 256;                 // 0..2047 16B chunks
            int isW = c >> 10, cc = c & 1023;    // 1024 chunks per operand
            int row = cc >> 3, seg = cc & 7;     // 128 rows x 8 segs(16B)
            const __nv_bfloat16* gp = isW
                ? Wp + (size_t)(n0 + row) * CC + kk + seg * 8
                : g_Abf + (size_t)(m0 + row) * CC + kk + seg * 8;
            uint32_t sp = (isW ? sW : sA) + (row * SA + seg * 8) * 2;
            asm volatile("cp.async.cg.shared.global [%0],[%1],16;\n" :: "r"(sp), "l"(gp));
        }
        asm volatile("cp.async.commit_group;\n");
    };

    const int aRow = lane & 15, aCol = (lane >> 4) << 3;
    const int bRow = (lane & 7) + ((lane >> 4) << 3), bCol = ((lane >> 3) & 1) << 3;

    prefetch(0, 0);
    prefetch(1, 1);

    #pragma unroll 1
    for (int it = 0; it < NIT; ++it) {
        if (it < NIT - 1) asm volatile("cp.async.wait_group 1;\n");
        else              asm volatile("cp.async.wait_group 0;\n");
        __syncthreads();
        if (it + 2 < NIT) prefetch(it + 2, (it + 2) % 3);

        const uint32_t sA = sBase + (it % 3) * STGSZ;
        const uint32_t sW = sA + OPSZ;
        #pragma unroll
        for (int ks = 0; ks < 4; ++ks) {
            unsigned a[2][4], bf[4][4];
            #pragma unroll
            for (int mt = 0; mt < 2; ++mt)
                ldsm4(a[mt], sA + ((wm * 32 + mt * 16 + aRow) * SA + ks * 16 + aCol) * 2);
            #pragma unroll
            for (int np = 0; np < 4; ++np)
                ldsm4(bf[np], sW + ((wn * 64 + np * 16 + bRow) * SA + ks * 16 + bCol) * 2);
            #pragma unroll
            for (int mt = 0; mt < 2; ++mt)
                #pragma unroll
                for (int j = 0; j < 8; ++j)
                    mma16816(acc[mt][j], a[mt], &bf[j >> 1][(j & 1) * 2]);
        }
    }

    // Epilogue: bias (+ exact GELU + 0.21 for Q/K)
    const int gid = lane >> 2, tid2 = lane & 3;
    #pragma unroll
    for (int mt = 0; mt < 2; ++mt) {
        int r0 = m0 + wm * 32 + mt * 16 + gid;
        #pragma unroll
        for (int j = 0; j < 8; ++j) {
            int col = n0 + wn * 64 + j * 8 + tid2 * 2;
            float b0 = __ldg(&bias[col]), b1 = __ldg(&bias[col + 1]);
            float y0 = acc[mt][j][0] + b0, y1 = acc[mt][j][1] + b1;
            float y2 = acc[mt][j][2] + b0, y3 = acc[mt][j][3] + b1;
            if (gel) {
                y0 = 0.5f * y0 * (1.f + erff(y0 * 0.7071067811865476f)) + 0.21f;
                y1 = 0.5f * y1 * (1.f + erff(y1 * 0.7071067811865476f)) + 0.21f;
                y2 = 0.5f * y2 * (1.f + erff(y2 * 0.7071067811865476f)) + 0.21f;
                y3 = 0.5f * y3 * (1.f + erff(y3 * 0.7071067811865476f)) + 0.21f;
            }
            *(float2*)&Y[(size_t)r0 * CC + col] = make_float2(y0, y1);
            *(float2*)&Y[(size_t)(r0 + 8) * CC + col] = make_float2(y2, y3);
        }
    }
}

// ---------------------------------------------------------------------------
// kv partial: per (b,h,split) accumulate  sum_n rope(k)[n,d]*v[n,e]  and sum_n k[n,d]
__global__ __launch_bounds__(256) void kv_partial_kernel() {
    int bh = blockIdx.x;
    int sp = blockIdx.y;
    int b = bh >> 4, h = bh & 15;
    int t = threadIdx.x;

    __shared__ float ks[32 * 64];
    __shared__ float krs[32 * 64];
    __shared__ float vs[32 * 64];

    int tx = t & 15, ty = t >> 4;
    float acc[4][4];
    #pragma unroll
    for (int i = 0; i < 4; i++)
        #pragma unroll
        for (int j = 0; j < 4; j++) acc[i][j] = 0.f;
    float ksum = 0.f;

    for (int ch = 0; ch < 8; ch++) {
        int n0 = sp * 256 + ch * 32;
        #pragma unroll
        for (int ld = 0; ld < 2; ld++) {
            int idx = t + ld * 256;
            int r = idx >> 4, c4 = idx & 15;
            size_t gofs = (size_t)(b * NN + n0 + r) * CC + h * DD + c4 * 4;
            *(float4*)&ks[r * 64 + c4 * 4] = *(const float4*)&g_K[gofs];
            *(float4*)&vs[r * 64 + c4 * 4] = *(const float4*)&g_V[gofs];
        }
        __syncthreads();
        #pragma unroll
        for (int pp = 0; pp < 4; pp++) {
            int p = t + pp * 256;
            int r = p >> 5, jj = p & 31;
            float a  = ks[r * 64 + 2 * jj];
            float bv = ks[r * 64 + 2 * jj + 1];
            int tofs = (n0 + r) * HALFC + h * 32 + jj;
            float cv = g_cos[tofs], sv = g_sin[tofs];
            krs[r * 64 + 2 * jj]     = a * cv - bv * sv;
            krs[r * 64 + 2 * jj + 1] = bv * cv + a * sv;
        }
        if (t < 64) {
            #pragma unroll
            for (int r = 0; r < 32; r++) ksum += ks[r * 64 + t];
        }
        __syncthreads();
        #pragma unroll
        for (int nn = 0; nn < 32; nn++) {
            float4 kr4 = *(float4*)&krs[nn * 64 + ty * 4];
            float4 vv4 = *(float4*)&vs[nn * 64 + tx * 4];
            float kr[4] = {kr4.x, kr4.y, kr4.z, kr4.w};
            float vv[4] = {vv4.x, vv4.y, vv4.z, vv4.w};
            #pragma unroll
            for (int i = 0; i < 4; i++)
                #pragma unroll
                for (int j = 0; j < 4; j++)
                    acc[i][j] += kr[i] * vv[j];
        }
        __syncthreads();
    }

    float* kvp = &g_kvp[((size_t)sp * (BB * HH) + bh) * (DD * DD)];
    #pragma unroll
    for (int i = 0; i < 4; i++)
        #pragma unroll
        for (int j = 0; j < 4; j++)
            kvp[(ty * 4 + i) * DD + tx * 4 + j] = acc[i][j];
    if (t < 64)
        g_kmp[((size_t)sp * (BB * HH) + bh) * DD + t] = ksum;
}

__global__ __launch_bounds__(256) void kv_reduce_kernel() {
    int bh = blockIdx.x;
    int t = threadIdx.x;
    const float inv = 1.f / (float)NN;
    for (int i = t; i < DD * DD; i += 256) {
        float s = 0.f;
        #pragma unroll
        for (int sp = 0; sp < NSPLIT; sp++)
            s += g_kvp[((size_t)sp * (BB * HH) + bh) * (DD * DD) + i];
        g_kv[(size_t)bh * (DD * DD) + i] = s * inv;
    }
    if (t < DD) {
        float s = 0.f;
        #pragma unroll
        for (int sp = 0; sp < NSPLIT; sp++)
            s += g_kmp[((size_t)sp * (BB * HH) + bh) * DD + t];
        g_km[(size_t)bh * DD + t] = s * inv;
    }
}

// ---------------------------------------------------------------------------
__global__ __launch_bounds__(256) void out_kernel() {
    int bh = blockIdx.x;
    int b = bh >> 4, h = bh & 15;
    int n0 = blockIdx.y * 32;
    int t = threadIdx.x;

    __shared__ float kvs[DD * DD];
    __shared__ float kms[DD];
    __shared__ float qs[16 * 64];
    __shared__ float qrs[16 * 64];

    #pragma unroll
    for (int ld = 0; ld < 4; ld++) {
        int i4 = t + ld * 256;
        *(float4*)&kvs[i4 * 4] = *(const float4*)&g_kv[(size_t)bh * (DD * DD) + i4 * 4];
    }
    if (t < DD) kms[t] = g_km[(size_t)bh * DD + t];
    __syncthreads();

    int tg = t & 15, rr = t >> 4;
    for (int ig = 0; ig < 2; ig++) {
        int n = n0 + ig * 16 + rr;
        *(float4*)&qs[rr * 64 + tg * 4] =
            *(const float4*)&g_Q[(size_t)(b * NN + n) * CC + h * DD + tg * 4];
        __syncthreads();
        #pragma unroll
        for (int pp = 0; pp < 2; pp++) {
            int p = t + pp * 256;
            int r = p >> 5, jj = p & 31;
            float a  = qs[r * 64 + 2 * jj];
            float bv = qs[r * 64 + 2 * jj + 1];
            int tofs = (n0 + ig * 16 + r) * HALFC + h * 32 + jj;
            float cv = g_cos[tofs], sv = g_sin[tofs];
            qrs[r * 64 + 2 * jj]     = a * cv - bv * sv;
            qrs[r * 64 + 2 * jj + 1] = bv * cv + a * sv;
        }
        float zacc = 0.f;
        #pragma unroll
        for (int d = 0; d < DD; d++) zacc += qs[rr * 64 + d] * kms[d];
        float z = 1.f / (zacc + 1e-6f);
        __syncthreads();
        float4 o = {0.f, 0.f, 0.f, 0.f};
        #pragma unroll
        for (int d = 0; d < DD; d++) {
            float qv = qrs[rr * 64 + d];
            float4 kvv = *(float4*)&kvs[d * 64 + tg * 4];
            o.x += qv * kvv.x; o.y += qv * kvv.y;
            o.z += qv * kvv.z; o.w += qv * kvv.w;
        }
        o.x *= z; o.y *= z; o.z *= z; o.w *= z;
        *(float4*)&g_O[(size_t)(b * NN + n) * CC + h * DD + tg * 4] = o;
        __syncthreads();
    }
}

// ---------------------------------------------------------------------------
__global__ __launch_bounds__(256) void ln_kernel(
    const float* __restrict__ x, const float* __restrict__ gamma,
    const float* __restrict__ beta, float* __restrict__ out)
{
    int row = blockIdx.x;
    int t = threadIdx.x;
    float4 a  = *(const float4*)&g_O[(size_t)row * CC + t * 4];
    float4 xv = *(const float4*)&x[(size_t)row * CC + t * 4];
    float4 r;
    r.x = a.x + xv.x; r.y = a.y + xv.y; r.z = a.z + xv.z; r.w = a.w + xv.w;
    float s  = r.x + r.y + r.z + r.w;
    float sq = r.x * r.x + r.y * r.y + r.z * r.z + r.w * r.w;
    #pragma unroll
    for (int off = 16; off; off >>= 1) {
        s  += __shfl_xor_sync(0xffffffffu, s, off);
        sq += __shfl_xor_sync(0xffffffffu, sq, off);
    }
    __shared__ float ss[8], ssq[8];
    __shared__ float mean_s, rstd_s;
    int w = t >> 5, lane = t & 31;
    if (lane == 0) { ss[w] = s; ssq[w] = sq; }
    __syncthreads();
    if (t == 0) {
        float S = 0.f, SQ = 0.f;
        #pragma unroll
        for (int i = 0; i < 8; i++) { S += ss[i]; SQ += ssq[i]; }
        float mean = S * (1.f / (float)CC);
        float var  = SQ * (1.f / (float)CC) - mean * mean;
        mean_s = mean;
        rstd_s = rsqrtf(var + 1e-12f);
    }
    __syncthreads();
    float mean = mean_s, rstd = rstd_s;
    float4 g  = *(const float4*)&gamma[t * 4];
    float4 be = *(const float4*)&beta[t * 4];
    float4 o;
    o.x = (r.x - mean) * rstd * g.x + be.x;
    o.y = (r.y - mean) * rstd * g.y + be.y;
    o.z = (r.z - mean) * rstd * g.z + be.z;
    o.w = (r.w - mean) * rstd * g.w + be.w;
    *(float4*)&out[(size_t)row * CC + t * 4] = o;
}

// ---------------------------------------------------------------------------
extern "C" void kernel_launch(void* const* d_in, const int* in_sizes, int n_in,
                              void* d_out, int out_size) {
    const float* x     = (const float*)d_in[0];
    const float* Wq    = (const float*)d_in[1];
    const float* bq    = (const float*)d_in[2];
    const float* Wk    = (const float*)d_in[3];
    const float* bk    = (const float*)d_in[4];
    const float* Wv    = (const float*)d_in[5];
    const float* bv    = (const float*)d_in[6];
    const float* gamma = (const float*)d_in[7];
    const float* beta  = (const float*)d_in[8];
    float* out = (float*)d_out;

    init_invfreq_kernel<<<1, 512>>>();
    init_rope_kernel<<<NN, 512>>>();

    conv_x_kernel<<<MM * CC / 1024, 256>>>(x);
    conv_w_kernel<<<dim3(CC * CC / 1024, 3), 256>>>(Wq, Wk, Wv);

    cudaFuncSetAttribute(gemm_mma_kernel,
                         cudaFuncAttributeMaxDynamicSharedMemorySize, GEMM_SMEM);
    dim3 ggrid(CC / 128, MM / 128, 3);               // (8, 128, 3)
    gemm_mma_kernel<<<ggrid, 256, GEMM_SMEM>>>(bq, bk, bv);

    kv_partial_kernel<<<dim3(BB * HH, NSPLIT), 256>>>();
    kv_reduce_kernel<<<BB * HH, 256>>>();
    out_kernel<<<dim3(BB * HH, NN / 32), 256>>>();
    ln_kernel<<<MM, 256>>>(x, gamma, beta, out);
}

// round 8
// speedup vs baseline: 2.5520x; 1.3162x over previous
#include <cuda_runtime.h>
#include <cuda_bf16.h>
#include <math.h>
#include <stdint.h>

// Problem constants
#define BB 8
#define NN 2048
#define CC 1024
#define HH 16
#define DD 64
#define MM (BB*NN)        // 16384 rows
#define HALFC (CC/2)

// Scratch (device globals: allocation-free per harness rules)
__device__ float  g_O[MM*CC];
__device__ float  g_kmp2[128*CC];          // per-mblock raw-K column sums
__device__ float  g_km[128*DD];            // [bh][d] k-mean (includes 1/N)
__device__ float  g_z[128*NN];             // [bh][n]
__device__ float  g_invfreq[HALFC];
__device__ float2 g_rope[NN*HALFC];        // (cos, sin)

// bf16 operands
__device__ __nv_bfloat16 g_Abf[MM*CC];
__device__ __nv_bfloat16 g_Wbf[3][CC*CC];
__device__ __nv_bfloat16 g_Qraw[MM*CC];    // [m][c] post-gelu raw q (for z)
__device__ __nv_bfloat16 g_Qr[MM*CC];      // [m][c] roped q
__device__ __nv_bfloat16 g_KrT[MM*CC];     // [bh][d][n] roped k transposed
__device__ __nv_bfloat16 g_VT[MM*CC];      // [bh][e][n] v transposed
__device__ __nv_bfloat16 g_kvT[128*DD*DD]; // [bh][e][d]

// ---------------------------------------------------------------------------
__global__ void init_invfreq_kernel() {
    int j = threadIdx.x;
    if (j < HALFC)
        g_invfreq[j] = (float)(1.0 / pow(10000.0, (double)(2 * j) / (double)CC));
}
__global__ __launch_bounds__(512) void init_rope_kernel() {
    int n = blockIdx.x;
    int j = threadIdx.x;
    float ang = (float)n * g_invfreq[j];
    float sv, cv;
    sincosf(ang, &sv, &cv);
    g_rope[n * HALFC + j] = make_float2(cv, sv);
}

// ---------------------------------------------------------------------------
__device__ __forceinline__ unsigned packbf2(float a, float b) {
    unsigned short lo = __bfloat16_as_ushort(__float2bfloat16(a));
    unsigned short hi = __bfloat16_as_ushort(__float2bfloat16(b));
    return (unsigned)lo | ((unsigned)hi << 16);
}

__global__ __launch_bounds__(256) void conv_x_kernel(const float* __restrict__ x) {
    size_t i = (size_t)blockIdx.x * 256 + threadIdx.x;
    float4 v = *(const float4*)(x + i * 4);
    uint2 u;
    u.x = packbf2(v.x, v.y); u.y = packbf2(v.z, v.w);
    *(uint2*)&g_Abf[i * 4] = u;
}
__global__ __launch_bounds__(256) void conv_w_kernel(
    const float* __restrict__ W0, const float* __restrict__ W1,
    const float* __restrict__ W2)
{
    int idx = blockIdx.y;
    const float* __restrict__ W = (idx == 0) ? W0 : (idx == 1) ? W1 : W2;
    size_t i = (size_t)blockIdx.x * 256 + threadIdx.x;
    float4 v = *(const float4*)(W + i * 4);
    uint2 u;
    u.x = packbf2(v.x, v.y); u.y = packbf2(v.z, v.w);
    *(uint2*)&g_Wbf[idx][i * 4] = u;
}

// ---------------------------------------------------------------------------
// MMA helpers
__device__ __forceinline__ void ldsm4(unsigned* r, uint32_t addr) {
    asm volatile("ldmatrix.sync.aligned.m8n8.x4.shared.b16 {%0,%1,%2,%3},[%4];\n"
                 : "=r"(r[0]), "=r"(r[1]), "=r"(r[2]), "=r"(r[3]) : "r"(addr));
}
__device__ __forceinline__ void mma16816(float* d, const unsigned* a, const unsigned* b) {
    asm volatile("mma.sync.aligned.m16n8k16.row.col.f32.bf16.bf16.f32 "
                 "{%0,%1,%2,%3},{%4,%5,%6,%7},{%8,%9},{%0,%1,%2,%3};\n"
                 : "+f"(d[0]), "+f"(d[1]), "+f"(d[2]), "+f"(d[3])
                 : "r"(a[0]), "r"(a[1]), "r"(a[2]), "r"(a[3]), "r"(b[0]), "r"(b[1]));
}
__device__ __forceinline__ void cp16(uint32_t sp, const void* gp) {
    asm volatile("cp.async.cg.shared.global [%0],[%1],16;\n" :: "r"(sp), "l"(gp));
}

// ---------------------------------------------------------------------------
// Main QKV GEMM. Tile 128x128, BK=64, 3-stage cp.async. blockIdx.z = which.
// Epilogue: Q -> Qraw bf16 + Qr bf16 ; K -> KrT bf16 (smem transpose) + ksum
// partials ; V -> VT bf16 (smem transpose).
#define SA 72
#define OPSZ (128 * SA * 2)
#define STGSZ (2 * OPSZ)
#define GEMM_SMEM (3 * STGSZ)      // 110592
#define NIT 16

__global__ __launch_bounds__(256, 2) void gemm_mma_kernel(
    const float* __restrict__ bq, const float* __restrict__ bk,
    const float* __restrict__ bv)
{
    extern __shared__ __nv_bfloat16 sm[];
    const int which = blockIdx.z;
    const float* __restrict__ bias = (which == 0) ? bq : (which == 1) ? bk : bv;
    const bool gel = (which < 2);
    const __nv_bfloat16* __restrict__ Wp = g_Wbf[which];

    const int t = threadIdx.x;
    const int lane = t & 31, warp = t >> 5;
    const int wm = warp & 3, wn = warp >> 2;
    const int m0 = blockIdx.y * 128, n0 = blockIdx.x * 128;
    const int b = m0 >> 11;

    const uint32_t sBase = (uint32_t)__cvta_generic_to_shared(sm);

    float acc[2][8][4];
    #pragma unroll
    for (int mt = 0; mt < 2; mt++)
        #pragma unroll
        for (int j = 0; j < 8; j++)
            #pragma unroll
            for (int r = 0; r < 4; r++) acc[mt][j][r] = 0.f;

    auto prefetch = [&](int it, int stg) {
        int kk = it << 6;
        uint32_t sA = sBase + stg * STGSZ;
        uint32_t sW = sA + OPSZ;
        #pragma unroll
        for (int i = 0; i < 8; i++) {
            int c = t + i * 256;
            int isW = c >> 10, cc = c & 1023;
            int row = cc >> 3, seg = cc & 7;
            const __nv_bfloat16* gp = isW
                ? Wp + (size_t)(n0 + row) * CC + kk + seg * 8
                : g_Abf + (size_t)(m0 + row) * CC + kk + seg * 8;
            cp16((isW ? sW : sA) + (row * SA + seg * 8) * 2, gp);
        }
        asm volatile("cp.async.commit_group;\n");
    };

    const int aRow = lane & 15, aCol = (lane >> 4) << 3;
    const int bRow = (lane & 7) + ((lane >> 4) << 3), bCol = ((lane >> 3) & 1) << 3;

    prefetch(0, 0);
    prefetch(1, 1);

    #pragma unroll 1
    for (int it = 0; it < NIT; ++it) {
        if (it < NIT - 1) asm volatile("cp.async.wait_group 1;\n");
        else              asm volatile("cp.async.wait_group 0;\n");
        __syncthreads();
        if (it + 2 < NIT) prefetch(it + 2, (it + 2) % 3);

        const uint32_t sA = sBase + (it % 3) * STGSZ;
        const uint32_t sW = sA + OPSZ;
        #pragma unroll
        for (int ks = 0; ks < 4; ++ks) {
            unsigned a[2][4], bf[4][4];
            #pragma unroll
            for (int mt = 0; mt < 2; ++mt)
                ldsm4(a[mt], sA + ((wm * 32 + mt * 16 + aRow) * SA + ks * 16 + aCol) * 2);
            #pragma unroll
            for (int np = 0; np < 4; ++np)
                ldsm4(bf[np], sW + ((wn * 64 + np * 16 + bRow) * SA + ks * 16 + bCol) * 2);
            #pragma unroll
            for (int mt = 0; mt < 2; ++mt)
                #pragma unroll
                for (int j = 0; j < 8; ++j)
                    mma16816(acc[mt][j], a[mt], &bf[j >> 1][(j & 1) * 2]);
        }
    }
    __syncthreads();     // smem free for epilogue staging

    const int gid = lane >> 2, tid2 = lane & 3;

    if (which == 0) {
        // Q: raw bf16 + roped bf16 writes
        #pragma unroll
        for (int mt = 0; mt < 2; ++mt) {
            int rl = wm * 32 + mt * 16 + gid;
            int m_lo = m0 + rl, m_hi = m_lo + 8;
            int nlo = m_lo & 2047, nhi = m_hi & 2047;
            #pragma unroll
            for (int j = 0; j < 8; ++j) {
                int c = n0 + wn * 64 + j * 8 + tid2 * 2;
                float b0 = __ldg(&bias[c]), b1 = __ldg(&bias[c + 1]);
                float y0 = acc[mt][j][0] + b0, y1 = acc[mt][j][1] + b1;
                float y2 = acc[mt][j][2] + b0, y3 = acc[mt][j][3] + b1;
                y0 = 0.5f * y0 * (1.f + erff(y0 * 0.7071067811865476f)) + 0.21f;
                y1 = 0.5f * y1 * (1.f + erff(y1 * 0.7071067811865476f)) + 0.21f;
                y2 = 0.5f * y2 * (1.f + erff(y2 * 0.7071067811865476f)) + 0.21f;
                y3 = 0.5f * y3 * (1.f + erff(y3 * 0.7071067811865476f)) + 0.21f;
                *(unsigned*)&g_Qraw[(size_t)m_lo * CC + c] = packbf2(y0, y1);
                *(unsigned*)&g_Qraw[(size_t)m_hi * CC + c] = packbf2(y2, y3);
                float2 rlc = g_rope[nlo * HALFC + (c >> 1)];
                float2 rhc = g_rope[nhi * HALFC + (c >> 1)];
                *(unsigned*)&g_Qr[(size_t)m_lo * CC + c] =
                    packbf2(y0 * rlc.x - y1 * rlc.y, y1 * rlc.x + y0 * rlc.y);
                *(unsigned*)&g_Qr[(size_t)m_hi * CC + c] =
                    packbf2(y2 * rhc.x - y3 * rhc.y, y3 * rhc.x + y2 * rhc.y);
            }
        }
    } else {
        // K/V: stage transposed tile sT[lc][r] then coalesced write
        __nv_bfloat16* sT = sm;                       // 128 x 136
        float* ksmem = (float*)(sm + 128 * 136);      // 4 x 128
        float ke[8], ko[8];
        #pragma unroll
        for (int j = 0; j < 8; ++j) { ke[j] = 0.f; ko[j] = 0.f; }

        #pragma unroll
        for (int mt = 0; mt < 2; ++mt) {
            int rl = wm * 32 + mt * 16 + gid;
            int m_lo = m0 + rl, m_hi = m_lo + 8;
            int nlo = m_lo & 2047, nhi = m_hi & 2047;
            #pragma unroll
            for (int j = 0; j < 8; ++j) {
                int lc = wn * 64 + j * 8 + tid2 * 2;
                int c = n0 + lc;
                float b0 = __ldg(&bias[c]), b1 = __ldg(&bias[c + 1]);
                float y0 = acc[mt][j][0] + b0, y1 = acc[mt][j][1] + b1;
                float y2 = acc[mt][j][2] + b0, y3 = acc[mt][j][3] + b1;
                if (gel) {   // K path
                    y0 = 0.5f * y0 * (1.f + erff(y0 * 0.7071067811865476f)) + 0.21f;
                    y1 = 0.5f * y1 * (1.f + erff(y1 * 0.7071067811865476f)) + 0.21f;
                    y2 = 0.5f * y2 * (1.f + erff(y2 * 0.7071067811865476f)) + 0.21f;
                    y3 = 0.5f * y3 * (1.f + erff(y3 * 0.7071067811865476f)) + 0.21f;
                    ke[j] += y0 + y2;  ko[j] += y1 + y3;
                    float2 rlc = g_rope[nlo * HALFC + (c >> 1)];
                    float2 rhc = g_rope[nhi * HALFC + (c >> 1)];
                    float k0 = y0 * rlc.x - y1 * rlc.y, k1 = y1 * rlc.x + y0 * rlc.y;
                    float k2 = y2 * rhc.x - y3 * rhc.y, k3 = y3 * rhc.x + y2 * rhc.y;
                    y0 = k0; y1 = k1; y2 = k2; y3 = k3;
                }
                sT[lc * 136 + rl]           = __float2bfloat16(y0);
                sT[(lc + 1) * 136 + rl]     = __float2bfloat16(y1);
                sT[lc * 136 + rl + 8]       = __float2bfloat16(y2);
                sT[(lc + 1) * 136 + rl + 8] = __float2bfloat16(y3);
            }
        }
        if (gel) {
            #pragma unroll
            for (int j = 0; j < 8; ++j) {
                float se = ke[j], so = ko[j];
                se += __shfl_down_sync(0xffffffffu, se, 4);
                se += __shfl_down_sync(0xffffffffu, se, 8);
                se += __shfl_down_sync(0xffffffffu, se, 16);
                so += __shfl_down_sync(0xffffffffu, so, 4);
                so += __shfl_down_sync(0xffffffffu, so, 8);
                so += __shfl_down_sync(0xffffffffu, so, 16);
                if (lane < 4) {
                    int lc = wn * 64 + j * 8 + tid2 * 2;
                    ksmem[wm * 128 + lc]     = se;
                    ksmem[wm * 128 + lc + 1] = so;
                }
            }
        }
        __syncthreads();
        if (gel && t < 128) {
            float s = ksmem[t] + ksmem[128 + t] + ksmem[256 + t] + ksmem[384 + t];
            g_kmp2[(size_t)blockIdx.y * CC + n0 + t] = s;
        }
        __nv_bfloat16* __restrict__ dst = gel ? g_KrT : g_VT;
        #pragma unroll
        for (int i = 0; i < 8; ++i) {
            int ii = t + i * 256;                 // 0..2047 uint4 slots
            int lc = ii >> 4, seg = ii & 15;
            int c = n0 + lc;
            int h = c >> 6, d = c & 63;
            uint4 v = *(uint4*)&sT[lc * 136 + seg * 8];
            *(uint4*)&dst[(((size_t)(b * 16 + h) * 64 + d) << 11) + (m0 & 2047) + seg * 8] = v;
        }
    }
}

// ---------------------------------------------------------------------------
// kmean: reduce per-mblock partials, apply 1/N
__global__ __launch_bounds__(256) void kmean_kernel() {
    int b = blockIdx.x;
    for (int c = threadIdx.x; c < CC; c += 256) {
        float s = 0.f;
        #pragma unroll
        for (int mb = 0; mb < 16; mb++)
            s += g_kmp2[(size_t)(b * 16 + mb) * CC + c];
        g_km[b * CC + c] = s * (1.f / (float)NN);
    }
}

// z[bh][n] = 1/(q_raw . km + 1e-6)
__global__ __launch_bounds__(256) void z_kernel() {
    int m0 = blockIdx.x * 16;
    int b = m0 >> 11;
    __shared__ float kms[CC];
    for (int i = threadIdx.x; i < CC; i += 256) kms[i] = g_km[b * CC + i];
    __syncthreads();
    int r = threadIdx.x >> 4, h = threadIdx.x & 15;
    int m = m0 + r;
    const __nv_bfloat16* qp = g_Qraw + (size_t)m * CC + h * 64;
    float s = 0.f;
    #pragma unroll
    for (int i = 0; i < 8; i++) {
        uint4 v = *(const uint4*)(qp + i * 8);
        unsigned u[4] = {v.x, v.y, v.z, v.w};
        #pragma unroll
        for (int k = 0; k < 4; k++) {
            float lo = __bfloat162float(__ushort_as_bfloat16((unsigned short)(u[k] & 0xffff)));
            float hi = __bfloat162float(__ushort_as_bfloat16((unsigned short)(u[k] >> 16)));
            s += lo * kms[h * 64 + i * 8 + k * 2] + hi * kms[h * 64 + i * 8 + k * 2 + 1];
        }
    }
    g_z[(size_t)(b * 16 + h) * NN + (m & 2047)] = 1.f / (s + 1e-6f);
}

// ---------------------------------------------------------------------------
// kv[d][e] = (1/N) sum_n KrT[d,n] * VT[e,n]  -> write kvT[e][d] bf16
#define KSA 72
__global__ __launch_bounds__(128) void kv_mma_kernel() {
    int bh = blockIdx.x;
    __shared__ __align__(16) __nv_bfloat16 sA[2][64 * KSA];
    __shared__ __align__(16) __nv_bfloat16 sB[2][64 * KSA];
    __shared__ __align__(16) __nv_bfloat16 sD[64 * 72];
    int t = threadIdx.x, lane = t & 31, warp = t >> 5;
    const __nv_bfloat16* Ap = g_KrT + (size_t)bh * 64 * NN;
    const __nv_bfloat16* Bp = g_VT + (size_t)bh * 64 * NN;
    const uint32_t a0 = (uint32_t)__cvta_generic_to_shared(&sA[0][0]);
    const uint32_t b0 = (uint32_t)__cvta_generic_to_shared(&sB[0][0]);

    float acc[8][4];
    #pragma unroll
    for (int j = 0; j < 8; j++)
        #pragma unroll
        for (int r = 0; r < 4; r++) acc[j][r] = 0.f;

    auto pf = [&](int it, int stg) {
        int nn = it * 64;
        #pragma unroll
        for (int i = 0; i < 4; i++) {
            int ii = t + i * 128;
            int row = ii >> 3, seg = ii & 7;
            cp16(a0 + (stg * 64 * KSA + row * KSA + seg * 8) * 2, Ap + (size_t)row * NN + nn + seg * 8);
            cp16(b0 + (stg * 64 * KSA + row * KSA + seg * 8) * 2, Bp + (size_t)row * NN + nn + seg * 8);
        }
        asm volatile("cp.async.commit_group;\n");
    };
    const int aRow = lane & 15, aCol = (lane >> 4) << 3;
    const int bRow = (lane & 7) + ((lane >> 4) << 3), bCol = ((lane >> 3) & 1) << 3;

    pf(0, 0);
    #pragma unroll 1
    for (int it = 0; it < 32; ++it) {
        asm volatile("cp.async.wait_group 0;\n");
        __syncthreads();
        if (it + 1 < 32) pf(it + 1, (it + 1) & 1);
        const uint32_t sa = a0 + (it & 1) * 64 * KSA * 2;
        const uint32_t sb = b0 + (it & 1) * 64 * KSA * 2;
        #pragma unroll
        for (int ks = 0; ks < 4; ++ks) {
            unsigned a[4], bf[4][4];
            ldsm4(a, sa + ((warp * 16 + aRow) * KSA + ks * 16 + aCol) * 2);
            #pragma unroll
            for (int np = 0; np < 4; ++np)
                ldsm4(bf[np], sb + ((np * 16 + bRow) * KSA + ks * 16 + bCol) * 2);
            #pragma unroll
            for (int j = 0; j < 8; ++j)
                mma16816(acc[j], a, &bf[j >> 1][(j & 1) * 2]);
        }
        __syncthreads();
    }
    // epilogue: scale 1/N, transpose to sD[e][d], write kvT
    const int gid = lane >> 2, tid2 = lane & 3;
    const float sc = 1.f / (float)NN;
    #pragma unroll
    for (int j = 0; j < 8; ++j) {
        int e = j * 8 + tid2 * 2;
        int d = warp * 16 + gid;
        sD[e * 72 + d]           = __float2bfloat16(acc[j][0] * sc);
        sD[(e + 1) * 72 + d]     = __float2bfloat16(acc[j][1] * sc);
        sD[e * 72 + d + 8]       = __float2bfloat16(acc[j][2] * sc);
        sD[(e + 1) * 72 + d + 8] = __float2bfloat16(acc[j][3] * sc);
    }
    __syncthreads();
    #pragma unroll
    for (int i = 0; i < 4; ++i) {
        int ii = t + i * 128;                 // 512 uint4 slots (64 x 8)
        int e = ii >> 3, seg = ii & 7;
        uint4 v = *(uint4*)&sD[e * 72 + seg * 8];
        *(uint4*)&g_kvT[(size_t)bh * 4096 + e * 64 + seg * 8] = v;
    }
}

// ---------------------------------------------------------------------------
// out[m][h*64+e] = z[bh][n] * sum_d Qr[m][h*64+d] * kvT[e][d]
__global__ __launch_bounds__(256) void out_mma_kernel() {
    int bh = blockIdx.x;
    int h = bh & 15;
    int m0 = (bh >> 4) * NN + blockIdx.y * 128;
    __shared__ __align__(16) __nv_bfloat16 sA[128 * 72];
    __shared__ __align__(16) __nv_bfloat16 sB[64 * 72];
    int t = threadIdx.x, lane = t & 31, warp = t >> 5;
    const uint32_t a0 = (uint32_t)__cvta_generic_to_shared(sA);
    const uint32_t b0 = (uint32_t)__cvta_generic_to_shared(sB);

    #pragma unroll
    for (int i = 0; i < 4; i++) {     // A: 128 rows x 8 segs
        int ii = t + i * 256;
        int row = ii >> 3, seg = ii & 7;
        cp16(a0 + (row * 72 + seg * 8) * 2,
             g_Qr + (size_t)(m0 + row) * CC + h * 64 + seg * 8);
    }
    #pragma unroll
    for (int i = 0; i < 2; i++) {     // B: 64 rows x 8 segs
        int ii = t + i * 256;
        int row = ii >> 3, seg = ii & 7;
        cp16(b0 + (row * 72 + seg * 8) * 2,
             g_kvT + (size_t)bh * 4096 + row * 64 + seg * 8);
    }
    asm volatile("cp.async.commit_group;\ncp.async.wait_group 0;\n");
    __syncthreads();

    const int aRow = lane & 15, aCol = (lane >> 4) << 3;
    const int bRow = (lane & 7) + ((lane >> 4) << 3), bCol = ((lane >> 3) & 1) << 3;
    float acc[8][4];
    #pragma unroll
    for (int j = 0; j < 8; j++)
        #pragma unroll
        for (int r = 0; r < 4; r++) acc[j][r] = 0.f;

    #pragma unroll
    for (int ks = 0; ks < 4; ++ks) {
        unsigned a[4], bf[4][4];
        ldsm4(a, a0 + ((warp * 16 + aRow) * 72 + ks * 16 + aCol) * 2);
        #pragma unroll
        for (int np = 0; np < 4; ++np)
            ldsm4(bf[np], b0 + ((np * 16 + bRow) * 72 + ks * 16 + bCol) * 2);
        #pragma unroll
        for (int j = 0; j < 8; ++j)
            mma16816(acc[j], a, &bf[j >> 1][(j & 1) * 2]);
    }

    const int gid = lane >> 2, tid2 = lane & 3;
    int m_lo = m0 + warp * 16 + gid, m_hi = m_lo + 8;
    float zl = g_z[(size_t)bh * NN + (m_lo & 2047)];
    float zh = g_z[(size_t)bh * NN + (m_hi & 2047)];
    #pragma unroll
    for (int j = 0; j < 8; ++j) {
        int c = h * 64 + j * 8 + tid2 * 2;
        *(float2*)&g_O[(size_t)m_lo * CC + c] = make_float2(acc[j][0] * zl, acc[j][1] * zl);
        *(float2*)&g_O[(size_t)m_hi * CC + c] = make_float2(acc[j][2] * zh, acc[j][3] * zh);
    }
}

// ---------------------------------------------------------------------------
__global__ __launch_bounds__(256) void ln_kernel(
    const float* __restrict__ x, const float* __restrict__ gamma,
    const float* __restrict__ beta, float* __restrict__ out)
{
    int row = blockIdx.x;
    int t = threadIdx.x;
    float4 a  = *(const float4*)&g_O[(size_t)row * CC + t * 4];
    float4 xv = *(const float4*)&x[(size_t)row * CC + t * 4];
    float4 r;
    r.x = a.x + xv.x; r.y = a.y + xv.y; r.z = a.z + xv.z; r.w = a.w + xv.w;
    float s  = r.x + r.y + r.z + r.w;
    float sq = r.x * r.x + r.y * r.y + r.z * r.z + r.w * r.w;
    #pragma unroll
    for (int off = 16; off; off >>= 1) {
        s  += __shfl_xor_sync(0xffffffffu, s, off);
        sq += __shfl_xor_sync(0xffffffffu, sq, off);
    }
    __shared__ float ss[8], ssq[8];
    __shared__ float mean_s, rstd_s;
    int w = t >> 5, lane = t & 31;
    if (lane == 0) { ss[w] = s; ssq[w] = sq; }
    __syncthreads();
    if (t == 0) {
        float S = 0.f, SQ = 0.f;
        #pragma unroll
        for (int i = 0; i < 8; i++) { S += ss[i]; SQ += ssq[i]; }
        float mean = S * (1.f / (float)CC);
        float var  = SQ * (1.f / (float)CC) - mean * mean;
        mean_s = mean;
        rstd_s = rsqrtf(var + 1e-12f);
    }
    __syncthreads();
    float mean = mean_s, rstd = rstd_s;
    float4 g  = *(const float4*)&gamma[t * 4];
    float4 be = *(const float4*)&beta[t * 4];
    float4 o;
    o.x = (r.x - mean) * rstd * g.x + be.x;
    o.y = (r.y - mean) * rstd * g.y + be.y;
    o.z = (r.z - mean) * rstd * g.z + be.z;
    o.w = (r.w - mean) * rstd * g.w + be.w;
    *(float4*)&out[(size_t)row * CC + t * 4] = o;
}

// ---------------------------------------------------------------------------
extern "C" void kernel_launch(void* const* d_in, const int* in_sizes, int n_in,
                              void* d_out, int out_size) {
    const float* x     = (const float*)d_in[0];
    const float* Wq    = (const float*)d_in[1];
    const float* bq    = (const float*)d_in[2];
    const float* Wk    = (const float*)d_in[3];
    const float* bk    = (const float*)d_in[4];
    const float* Wv    = (const float*)d_in[5];
    const float* bv    = (const float*)d_in[6];
    const float* gamma = (const float*)d_in[7];
    const float* beta  = (const float*)d_in[8];
    float* out = (float*)d_out;

    init_invfreq_kernel<<<1, 512>>>();
    init_rope_kernel<<<NN, 512>>>();

    conv_x_kernel<<<MM * CC / 1024, 256>>>(x);
    conv_w_kernel<<<dim3(CC * CC / 1024, 3), 256>>>(Wq, Wk, Wv);

    cudaFuncSetAttribute(gemm_mma_kernel,
                         cudaFuncAttributeMaxDynamicSharedMemorySize, GEMM_SMEM);
    dim3 ggrid(CC / 128, MM / 128, 3);
    gemm_mma_kernel<<<ggrid, 256, GEMM_SMEM>>>(bq, bk, bv);

    kmean_kernel<<<BB, 256>>>();
    z_kernel<<<MM / 16, 256>>>();
    kv_mma_kernel<<<128, 128>>>();
    out_mma_kernel<<<dim3(128, NN / 128), 256>>>();
    ln_kernel<<<MM, 256>>>(x, gamma, beta, out);
}

// round 9
// speedup vs baseline: 2.7697x; 1.0853x over previous
#include <cuda_runtime.h>
#include <cuda_bf16.h>
#include <math.h>
#include <stdint.h>

// Problem constants
#define BB 8
#define NN 2048
#define CC 1024
#define HH 16
#define DD 64
#define MM (BB*NN)        // 16384 rows
#define HALFC (CC/2)

// Scratch (device globals: allocation-free per harness rules)
__device__ float  g_kmp2[128*CC];          // per-mblock raw-K column sums
__device__ float  g_km[128*DD];            // [b][c] k-mean (includes 1/N)
__device__ float  g_invfreq[HALFC];
__device__ float2 g_rope[NN*HALFC];        // (cos, sin)

// bf16 operands
__device__ __nv_bfloat16 g_Abf[MM*CC];
__device__ __nv_bfloat16 g_Wbf[3][CC*CC];
__device__ __nv_bfloat16 g_Qraw[MM*CC];    // [m][c] post-gelu raw q (for z)
__device__ __nv_bfloat16 g_Qr[MM*CC];      // [m][c] roped q
__device__ __nv_bfloat16 g_KrT[MM*CC];     // [bh][d][n] roped k transposed
__device__ __nv_bfloat16 g_VT[MM*CC];      // [bh][e][n] v transposed
__device__ __nv_bfloat16 g_kvT[128*DD*DD]; // [bh][e][d]
__device__ __nv_bfloat16 g_O16[MM*CC];     // attention output (pre-residual)

// ---------------------------------------------------------------------------
__global__ void init_invfreq_kernel() {
    int j = threadIdx.x;
    if (j < HALFC)
        g_invfreq[j] = (float)(1.0 / pow(10000.0, (double)(2 * j) / (double)CC));
}
__global__ __launch_bounds__(512) void init_rope_kernel() {
    int n = blockIdx.x;
    int j = threadIdx.x;
    float ang = (float)n * g_invfreq[j];
    float sv, cv;
    sincosf(ang, &sv, &cv);
    g_rope[n * HALFC + j] = make_float2(cv, sv);
}

// ---------------------------------------------------------------------------
__device__ __forceinline__ unsigned packbf2(float a, float b) {
    unsigned short lo = __bfloat16_as_ushort(__float2bfloat16(a));
    unsigned short hi = __bfloat16_as_ushort(__float2bfloat16(b));
    return (unsigned)lo | ((unsigned)hi << 16);
}

// Combined fp32->bf16 conversion: blocks 0..16383 -> x, then 1024 each for W0..W2
__global__ __launch_bounds__(256) void conv_all_kernel(
    const float* __restrict__ x, const float* __restrict__ W0,
    const float* __restrict__ W1, const float* __restrict__ W2)
{
    int blk = blockIdx.x;
    const float* __restrict__ src;
    __nv_bfloat16* __restrict__ dst;
    size_t base;
    if (blk < 16384) { src = x; dst = g_Abf; base = (size_t)blk * 256; }
    else {
        int w = (blk - 16384) >> 10;
        int bb = (blk - 16384) & 1023;
        src = (w == 0) ? W0 : (w == 1) ? W1 : W2;
        dst = g_Wbf[w];
        base = (size_t)bb * 256;
    }
    size_t i = base + threadIdx.x;
    float4 v = *(const float4*)(src + i * 4);
    uint2 u;
    u.x = packbf2(v.x, v.y); u.y = packbf2(v.z, v.w);
    *(uint2*)&dst[i * 4] = u;
}

// ---------------------------------------------------------------------------
// MMA helpers
__device__ __forceinline__ void ldsm4(unsigned* r, uint32_t addr) {
    asm volatile("ldmatrix.sync.aligned.m8n8.x4.shared.b16 {%0,%1,%2,%3},[%4];\n"
                 : "=r"(r[0]), "=r"(r[1]), "=r"(r[2]), "=r"(r[3]) : "r"(addr));
}
__device__ __forceinline__ void mma16816(float* d, const unsigned* a, const unsigned* b) {
    asm volatile("mma.sync.aligned.m16n8k16.row.col.f32.bf16.bf16.f32 "
                 "{%0,%1,%2,%3},{%4,%5,%6,%7},{%8,%9},{%0,%1,%2,%3};\n"
                 : "+f"(d[0]), "+f"(d[1]), "+f"(d[2]), "+f"(d[3])
                 : "r"(a[0]), "r"(a[1]), "r"(a[2]), "r"(a[3]), "r"(b[0]), "r"(b[1]));
}
__device__ __forceinline__ void cp16(uint32_t sp, const void* gp) {
    asm volatile("cp.async.cg.shared.global [%0],[%1],16;\n" :: "r"(sp), "l"(gp));
}

// ---------------------------------------------------------------------------
// Main QKV GEMM. Tile 128x128, BK=64, 3-stage cp.async. blockIdx.z = which.
#define SA 72
#define OPSZ (128 * SA * 2)
#define STGSZ (2 * OPSZ)
#define GEMM_SMEM (3 * STGSZ)      // 110592
#define NIT 16

__global__ __launch_bounds__(256, 2) void gemm_mma_kernel(
    const float* __restrict__ bq, const float* __restrict__ bk,
    const float* __restrict__ bv)
{
    extern __shared__ __nv_bfloat16 sm[];
    const int which = blockIdx.z;
    const float* __restrict__ bias = (which == 0) ? bq : (which == 1) ? bk : bv;
    const bool gel = (which < 2);
    const __nv_bfloat16* __restrict__ Wp = g_Wbf[which];

    const int t = threadIdx.x;
    const int lane = t & 31, warp = t >> 5;
    const int wm = warp & 3, wn = warp >> 2;
    const int m0 = blockIdx.y * 128, n0 = blockIdx.x * 128;
    const int b = m0 >> 11;

    const uint32_t sBase = (uint32_t)__cvta_generic_to_shared(sm);

    float acc[2][8][4];
    #pragma unroll
    for (int mt = 0; mt < 2; mt++)
        #pragma unroll
        for (int j = 0; j < 8; j++)
            #pragma unroll
            for (int r = 0; r < 4; r++) acc[mt][j][r] = 0.f;

    auto prefetch = [&](int it, int stg) {
        int kk = it << 6;
        uint32_t sA = sBase + stg * STGSZ;
        uint32_t sW = sA + OPSZ;
        #pragma unroll
        for (int i = 0; i < 8; i++) {
            int c = t + i * 256;
            int isW = c >> 10, cc = c & 1023;
            int row = cc >> 3, seg = cc & 7;
            const __nv_bfloat16* gp = isW
                ? Wp + (size_t)(n0 + row) * CC + kk + seg * 8
                : g_Abf + (size_t)(m0 + row) * CC + kk + seg * 8;
            cp16((isW ? sW : sA) + (row * SA + seg * 8) * 2, gp);
        }
        asm volatile("cp.async.commit_group;\n");
    };

    const int aRow = lane & 15, aCol = (lane >> 4) << 3;
    const int bRow = (lane & 7) + ((lane >> 4) << 3), bCol = ((lane >> 3) & 1) << 3;

    prefetch(0, 0);
    prefetch(1, 1);

    #pragma unroll 1
    for (int it = 0; it < NIT; ++it) {
        if (it < NIT - 1) asm volatile("cp.async.wait_group 1;\n");
        else              asm volatile("cp.async.wait_group 0;\n");
        __syncthreads();
        if (it + 2 < NIT) prefetch(it + 2, (it + 2) % 3);

        const uint32_t sA = sBase + (it % 3) * STGSZ;
        const uint32_t sW = sA + OPSZ;
        #pragma unroll
        for (int ks = 0; ks < 4; ++ks) {
            unsigned a[2][4], bf[4][4];
            #pragma unroll
            for (int mt = 0; mt < 2; ++mt)
                ldsm4(a[mt], sA + ((wm * 32 + mt * 16 + aRow) * SA + ks * 16 + aCol) * 2);
            #pragma unroll
            for (int np = 0; np < 4; ++np)
                ldsm4(bf[np], sW + ((wn * 64 + np * 16 + bRow) * SA + ks * 16 + bCol) * 2);
            #pragma unroll
            for (int mt = 0; mt < 2; ++mt)
                #pragma unroll
                for (int j = 0; j < 8; ++j)
                    mma16816(acc[mt][j], a[mt], &bf[j >> 1][(j & 1) * 2]);
        }
    }
    __syncthreads();     // smem free for epilogue staging

    const int gid = lane >> 2, tid2 = lane & 3;

    if (which == 0) {
        // Q: raw bf16 + roped bf16 writes
        #pragma unroll
        for (int mt = 0; mt < 2; ++mt) {
            int rl = wm * 32 + mt * 16 + gid;
            int m_lo = m0 + rl, m_hi = m_lo + 8;
            int nlo = m_lo & 2047, nhi = m_hi & 2047;
            #pragma unroll
            for (int j = 0; j < 8; ++j) {
                int c = n0 + wn * 64 + j * 8 + tid2 * 2;
                float b0 = __ldg(&bias[c]), b1 = __ldg(&bias[c + 1]);
                float y0 = acc[mt][j][0] + b0, y1 = acc[mt][j][1] + b1;
                float y2 = acc[mt][j][2] + b0, y3 = acc[mt][j][3] + b1;
                y0 = 0.5f * y0 * (1.f + erff(y0 * 0.7071067811865476f)) + 0.21f;
                y1 = 0.5f * y1 * (1.f + erff(y1 * 0.7071067811865476f)) + 0.21f;
                y2 = 0.5f * y2 * (1.f + erff(y2 * 0.7071067811865476f)) + 0.21f;
                y3 = 0.5f * y3 * (1.f + erff(y3 * 0.7071067811865476f)) + 0.21f;
                *(unsigned*)&g_Qraw[(size_t)m_lo * CC + c] = packbf2(y0, y1);
                *(unsigned*)&g_Qraw[(size_t)m_hi * CC + c] = packbf2(y2, y3);
                float2 rlc = g_rope[nlo * HALFC + (c >> 1)];
                float2 rhc = g_rope[nhi * HALFC + (c >> 1)];
                *(unsigned*)&g_Qr[(size_t)m_lo * CC + c] =
                    packbf2(y0 * rlc.x - y1 * rlc.y, y1 * rlc.x + y0 * rlc.y);
                *(unsigned*)&g_Qr[(size_t)m_hi * CC + c] =
                    packbf2(y2 * rhc.x - y3 * rhc.y, y3 * rhc.x + y2 * rhc.y);
            }
        }
    } else {
        // K/V: stage transposed tile sT[lc][r] then coalesced write
        __nv_bfloat16* sT = sm;                       // 128 x 136
        float* ksmem = (float*)(sm + 128 * 136);      // 4 x 128
        float ke[8], ko[8];
        #pragma unroll
        for (int j = 0; j < 8; ++j) { ke[j] = 0.f; ko[j] = 0.f; }

        #pragma unroll
        for (int mt = 0; mt < 2; ++mt) {
            int rl = wm * 32 + mt * 16 + gid;
            int m_lo = m0 + rl, m_hi = m_lo + 8;
            int nlo = m_lo & 2047, nhi = m_hi & 2047;
            #pragma unroll
            for (int j = 0; j < 8; ++j) {
                int lc = wn * 64 + j * 8 + tid2 * 2;
                int c = n0 + lc;
                float b0 = __ldg(&bias[c]), b1 = __ldg(&bias[c + 1]);
                float y0 = acc[mt][j][0] + b0, y1 = acc[mt][j][1] + b1;
                float y2 = acc[mt][j][2] + b0, y3 = acc[mt][j][3] + b1;
                if (gel) {   // K path
                    y0 = 0.5f * y0 * (1.f + erff(y0 * 0.7071067811865476f)) + 0.21f;
                    y1 = 0.5f * y1 * (1.f + erff(y1 * 0.7071067811865476f)) + 0.21f;
                    y2 = 0.5f * y2 * (1.f + erff(y2 * 0.7071067811865476f)) + 0.21f;
                    y3 = 0.5f * y3 * (1.f + erff(y3 * 0.7071067811865476f)) + 0.21f;
                    ke[j] += y0 + y2;  ko[j] += y1 + y3;
                    float2 rlc = g_rope[nlo * HALFC + (c >> 1)];
                    float2 rhc = g_rope[nhi * HALFC + (c >> 1)];
                    float k0 = y0 * rlc.x - y1 * rlc.y, k1 = y1 * rlc.x + y0 * rlc.y;
                    float k2 = y2 * rhc.x - y3 * rhc.y, k3 = y3 * rhc.x + y2 * rhc.y;
                    y0 = k0; y1 = k1; y2 = k2; y3 = k3;
                }
                sT[lc * 136 + rl]           = __float2bfloat16(y0);
                sT[(lc + 1) * 136 + rl]     = __float2bfloat16(y1);
                sT[lc * 136 + rl + 8]       = __float2bfloat16(y2);
                sT[(lc + 1) * 136 + rl + 8] = __float2bfloat16(y3);
            }
        }
        if (gel) {
            #pragma unroll
            for (int j = 0; j < 8; ++j) {
                float se = ke[j], so = ko[j];
                se += __shfl_down_sync(0xffffffffu, se, 4);
                se += __shfl_down_sync(0xffffffffu, se, 8);
                se += __shfl_down_sync(0xffffffffu, se, 16);
                so += __shfl_down_sync(0xffffffffu, so, 4);
                so += __shfl_down_sync(0xffffffffu, so, 8);
                so += __shfl_down_sync(0xffffffffu, so, 16);
                if (lane < 4) {
                    int lc = wn * 64 + j * 8 + tid2 * 2;
                    ksmem[wm * 128 + lc]     = se;
                    ksmem[wm * 128 + lc + 1] = so;
                }
            }
        }
        __syncthreads();
        if (gel && t < 128) {
            float s = ksmem[t] + ksmem[128 + t] + ksmem[256 + t] + ksmem[384 + t];
            g_kmp2[(size_t)blockIdx.y * CC + n0 + t] = s;
        }
        __nv_bfloat16* __restrict__ dst = gel ? g_KrT : g_VT;
        #pragma unroll
        for (int i = 0; i < 8; ++i) {
            int ii = t + i * 256;                 // 0..2047 uint4 slots
            int lc = ii >> 4, seg = ii & 15;
            int c = n0 + lc;
            int h = c >> 6, d = c & 63;
            uint4 v = *(uint4*)&sT[lc * 136 + seg * 8];
            *(uint4*)&dst[(((size_t)(b * 16 + h) * 64 + d) << 11) + (m0 & 2047) + seg * 8] = v;
        }
    }
}

// ---------------------------------------------------------------------------
// kmean: reduce per-mblock partials, apply 1/N
__global__ __launch_bounds__(256) void kmean_kernel() {
    int b = blockIdx.x;
    for (int c = threadIdx.x; c < CC; c += 256) {
        float s = 0.f;
        #pragma unroll
        for (int mb = 0; mb < 16; mb++)
            s += g_kmp2[(size_t)(b * 16 + mb) * CC + c];
        g_km[b * CC + c] = s * (1.f / (float)NN);
    }
}

// ---------------------------------------------------------------------------
// kv[d][e] = (1/N) sum_n KrT[d,n] * VT[e,n]  -> write kvT[e][d] bf16
// 3-stage cp.async pipeline, dynamic smem.
#define KSA 72
#define KVOP (64 * KSA * 2)            // 9216 per operand per stage
#define KVSTG (2 * KVOP)               // 18432
#define KV_SMEM (3 * KVSTG)            // 55296
__global__ __launch_bounds__(128) void kv_mma_kernel() {
    extern __shared__ __nv_bfloat16 ksm[];
    int bh = blockIdx.x;
    int t = threadIdx.x, lane = t & 31, warp = t >> 5;
    const __nv_bfloat16* Ap = g_KrT + (size_t)bh * 64 * NN;
    const __nv_bfloat16* Bp = g_VT + (size_t)bh * 64 * NN;
    const uint32_t s0 = (uint32_t)__cvta_generic_to_shared(ksm);

    float acc[8][4];
    #pragma unroll
    for (int j = 0; j < 8; j++)
        #pragma unroll
        for (int r = 0; r < 4; r++) acc[j][r] = 0.f;

    auto pf = [&](int it, int stg) {
        int nn = it * 64;
        uint32_t sa = s0 + stg * KVSTG;
        uint32_t sb = sa + KVOP;
        #pragma unroll
        for (int i = 0; i < 4; i++) {
            int ii = t + i * 128;
            int row = ii >> 3, seg = ii & 7;
            cp16(sa + (row * KSA + seg * 8) * 2, Ap + (size_t)row * NN + nn + seg * 8);
            cp16(sb + (row * KSA + seg * 8) * 2, Bp + (size_t)row * NN + nn + seg * 8);
        }
        asm volatile("cp.async.commit_group;\n");
    };
    const int aRow = lane & 15, aCol = (lane >> 4) << 3;
    const int bRow = (lane & 7) + ((lane >> 4) << 3), bCol = ((lane >> 3) & 1) << 3;

    pf(0, 0);
    pf(1, 1);
    #pragma unroll 1
    for (int it = 0; it < 32; ++it) {
        if (it < 31) asm volatile("cp.async.wait_group 1;\n");
        else         asm volatile("cp.async.wait_group 0;\n");
        __syncthreads();
        if (it + 2 < 32) pf(it + 2, (it + 2) % 3);
        const uint32_t sa = s0 + (it % 3) * KVSTG;
        const uint32_t sb = sa + KVOP;
        #pragma unroll
        for (int ks = 0; ks < 4; ++ks) {
            unsigned a[4], bf[4][4];
            ldsm4(a, sa + ((warp * 16 + aRow) * KSA + ks * 16 + aCol) * 2);
            #pragma unroll
            for (int np = 0; np < 4; ++np)
                ldsm4(bf[np], sb + ((np * 16 + bRow) * KSA + ks * 16 + bCol) * 2);
            #pragma unroll
            for (int j = 0; j < 8; ++j)
                mma16816(acc[j], a, &bf[j >> 1][(j & 1) * 2]);
        }
    }
    __syncthreads();
    // epilogue: scale 1/N, transpose to sD[e][d], write kvT (sD reuses stage 0)
    __nv_bfloat16* sD = ksm;       // 64 x 72
    const int gid = lane >> 2, tid2 = lane & 3;
    const float sc = 1.f / (float)NN;
    #pragma unroll
    for (int j = 0; j < 8; ++j) {
        int e = j * 8 + tid2 * 2;
        int d = warp * 16 + gid;
        sD[e * 72 + d]           = __float2bfloat16(acc[j][0] * sc);
        sD[(e + 1) * 72 + d]     = __float2bfloat16(acc[j][1] * sc);
        sD[e * 72 + d + 8]       = __float2bfloat16(acc[j][2] * sc);
        sD[(e + 1) * 72 + d + 8] = __float2bfloat16(acc[j][3] * sc);
    }
    __syncthreads();
    #pragma unroll
    for (int i = 0; i < 4; ++i) {
        int ii = t + i * 128;                 // 512 uint4 slots (64 x 8)
        int e = ii >> 3, seg = ii & 7;
        uint4 v = *(uint4*)&sD[e * 72 + seg * 8];
        *(uint4*)&g_kvT[(size_t)bh * 4096 + e * 64 + seg * 8] = v;
    }
}

// ---------------------------------------------------------------------------
// out[m][h*64+e] = z[m,h] * sum_d Qr[m][h*64+d] * kvT[e][d]  (z fused in)
__global__ __launch_bounds__(256) void out_mma_kernel() {
    int bh = blockIdx.x;
    int h = bh & 15, b = bh >> 4;
    int m0 = b * NN + blockIdx.y * 128;
    __shared__ __align__(16) __nv_bfloat16 sA[128 * 72];
    __shared__ __align__(16) __nv_bfloat16 sB[64 * 72];
    __shared__ float kms[64];
    __shared__ float zv[128];
    int t = threadIdx.x, lane = t & 31, warp = t >> 5;
    const uint32_t a0 = (uint32_t)__cvta_generic_to_shared(sA);
    const uint32_t b0 = (uint32_t)__cvta_generic_to_shared(sB);

    #pragma unroll
    for (int i = 0; i < 4; i++) {     // A: 128 rows x 8 segs
        int ii = t + i * 256;
        int row = ii >> 3, seg = ii & 7;
        cp16(a0 + (row * 72 + seg * 8) * 2,
             g_Qr + (size_t)(m0 + row) * CC + h * 64 + seg * 8);
    }
    #pragma unroll
    for (int i = 0; i < 2; i++) {     // B: 64 rows x 8 segs
        int ii = t + i * 256;
        int row = ii >> 3, seg = ii & 7;
        cp16(b0 + (row * 72 + seg * 8) * 2,
             g_kvT + (size_t)bh * 4096 + row * 64 + seg * 8);
    }
    asm volatile("cp.async.commit_group;\n");

    // z computation in cp.async shadow
    if (t < 64) kms[t] = g_km[b * CC + h * 64 + t];
    __syncthreads();
    if (t < 128) {
        const __nv_bfloat16* qp = g_Qraw + (size_t)(m0 + t) * CC + h * 64;
        float s = 0.f;
        #pragma unroll
        for (int i = 0; i < 8; i++) {
            uint4 v = *(const uint4*)(qp + i * 8);
            unsigned u[4] = {v.x, v.y, v.z, v.w};
            #pragma unroll
            for (int k = 0; k < 4; k++) {
                float lo = __bfloat162float(__ushort_as_bfloat16((unsigned short)(u[k] & 0xffff)));
                float hi = __bfloat162float(__ushort_as_bfloat16((unsigned short)(u[k] >> 16)));
                s += lo * kms[i * 8 + k * 2] + hi * kms[i * 8 + k * 2 + 1];
            }
        }
        zv[t] = 1.f / (s + 1e-6f);
    }
    asm volatile("cp.async.wait_group 0;\n");
    __syncthreads();

    const int aRow = lane & 15, aCol = (lane >> 4) << 3;
    const int bRow = (lane & 7) + ((lane >> 4) << 3), bCol = ((lane >> 3) & 1) << 3;
    float acc[8][4];
    #pragma unroll
    for (int j = 0; j < 8; j++)
        #pragma unroll
        for (int r = 0; r < 4; r++) acc[j][r] = 0.f;

    #pragma unroll
    for (int ks = 0; ks < 4; ++ks) {
        unsigned a[4], bf[4][4];
        ldsm4(a, a0 + ((warp * 16 + aRow) * 72 + ks * 16 + aCol) * 2);
        #pragma unroll
        for (int np = 0; np < 4; ++np)
            ldsm4(bf[np], b0 + ((np * 16 + bRow) * 72 + ks * 16 + bCol) * 2);
        #pragma unroll
        for (int j = 0; j < 8; ++j)
            mma16816(acc[j], a, &bf[j >> 1][(j & 1) * 2]);
    }

    const int gid = lane >> 2, tid2 = lane & 3;
    int rl = warp * 16 + gid;
    int m_lo = m0 + rl, m_hi = m_lo + 8;
    float zl = zv[rl], zh = zv[rl + 8];
    #pragma unroll
    for (int j = 0; j < 8; ++j) {
        int c = h * 64 + j * 8 + tid2 * 2;
        *(unsigned*)&g_O16[(size_t)m_lo * CC + c] = packbf2(acc[j][0] * zl, acc[j][1] * zl);
        *(unsigned*)&g_O16[(size_t)m_hi * CC + c] = packbf2(acc[j][2] * zh, acc[j][3] * zh);
    }
}

// ---------------------------------------------------------------------------
__global__ __launch_bounds__(256) void ln_kernel(
    const float* __restrict__ x, const float* __restrict__ gamma,
    const float* __restrict__ beta, float* __restrict__ out)
{
    int row = blockIdx.x;
    int t = threadIdx.x;
    uint2 ou = *(const uint2*)&g_O16[(size_t)row * CC + t * 4];
    float4 xv = *(const float4*)&x[(size_t)row * CC + t * 4];
    float4 r;
    r.x = xv.x + __bfloat162float(__ushort_as_bfloat16((unsigned short)(ou.x & 0xffff)));
    r.y = xv.y + __bfloat162float(__ushort_as_bfloat16((unsigned short)(ou.x >> 16)));
    r.z = xv.z + __bfloat162float(__ushort_as_bfloat16((unsigned short)(ou.y & 0xffff)));
    r.w = xv.w + __bfloat162float(__ushort_as_bfloat16((unsigned short)(ou.y >> 16)));
    float s  = r.x + r.y + r.z + r.w;
    float sq = r.x * r.x + r.y * r.y + r.z * r.z + r.w * r.w;
    #pragma unroll
    for (int off = 16; off; off >>= 1) {
        s  += __shfl_xor_sync(0xffffffffu, s, off);
        sq += __shfl_xor_sync(0xffffffffu, sq, off);
    }
    __shared__ float ss[8], ssq[8];
    __shared__ float mean_s, rstd_s;
    int w = t >> 5, lane = t & 31;
    if (lane == 0) { ss[w] = s; ssq[w] = sq; }
    __syncthreads();
    if (t == 0) {
        float S = 0.f, SQ = 0.f;
        #pragma unroll
        for (int i = 0; i < 8; i++) { S += ss[i]; SQ += ssq[i]; }
        float mean = S * (1.f / (float)CC);
        float var  = SQ * (1.f / (float)CC) - mean * mean;
        mean_s = mean;
        rstd_s = rsqrtf(var + 1e-12f);
    }
    __syncthreads();
    float mean = mean_s, rstd = rstd_s;
    float4 g  = *(const float4*)&gamma[t * 4];
    float4 be = *(const float4*)&beta[t * 4];
    float4 o;
    o.x = (r.x - mean) * rstd * g.x + be.x;
    o.y = (r.y - mean) * rstd * g.y + be.y;
    o.z = (r.z - mean) * rstd * g.z + be.z;
    o.w = (r.w - mean) * rstd * g.w + be.w;
    *(float4*)&out[(size_t)row * CC + t * 4] = o;
}

// ---------------------------------------------------------------------------
extern "C" void kernel_launch(void* const* d_in, const int* in_sizes, int n_in,
                              void* d_out, int out_size) {
    const float* x     = (const float*)d_in[0];
    const float* Wq    = (const float*)d_in[1];
    const float* bq    = (const float*)d_in[2];
    const float* Wk    = (const float*)d_in[3];
    const float* bk    = (const float*)d_in[4];
    const float* Wv    = (const float*)d_in[5];
    const float* bv    = (const float*)d_in[6];
    const float* gamma = (const float*)d_in[7];
    const float* beta  = (const float*)d_in[8];
    float* out = (float*)d_out;

    init_invfreq_kernel<<<1, 512>>>();
    init_rope_kernel<<<NN, 512>>>();
    conv_all_kernel<<<16384 + 3 * 1024, 256>>>(x, Wq, Wk, Wv);

    cudaFuncSetAttribute(gemm_mma_kernel,
                         cudaFuncAttributeMaxDynamicSharedMemorySize, GEMM_SMEM);
    dim3 ggrid(CC / 128, MM / 128, 3);
    gemm_mma_kernel<<<ggrid, 256, GEMM_SMEM>>>(bq, bk, bv);   // 4th launch -> profiled

    kmean_kernel<<<BB, 256>>>();
    cudaFuncSetAttribute(kv_mma_kernel,
                         cudaFuncAttributeMaxDynamicSharedMemorySize, KV_SMEM);
    kv_mma_kernel<<<128, 128, KV_SMEM>>>();
    out_mma_kernel<<<dim3(128, NN / 128), 256>>>();
    ln_kernel<<<MM, 256>>>(x, gamma, beta, out);
}

// round 10
// speedup vs baseline: 2.7808x; 1.0040x over previous
#include <cuda_runtime.h>
#include <cuda_bf16.h>
#include <math.h>
#include <stdint.h>

// Problem constants
#define BB 8
#define NN 2048
#define CC 1024
#define HH 16
#define DD 64
#define MM (BB*NN)        // 16384 rows
#define HALFC (CC/2)

// Scratch (device globals: allocation-free per harness rules)
__device__ float  g_kmp2[128*CC];          // per-mblock raw-K column sums
__device__ float  g_km[128*DD];            // [b][c] k-mean (includes 1/N)
__device__ float  g_invfreq[HALFC];
__device__ float2 g_rope[NN*HALFC];        // (cos, sin)

// bf16 operands
__device__ __nv_bfloat16 g_Abf[MM*CC];
__device__ __nv_bfloat16 g_Wbf[3][CC*CC];
__device__ __nv_bfloat16 g_Qraw[MM*CC];    // [m][c] post-gelu raw q (for z)
__device__ __nv_bfloat16 g_Qr[MM*CC];      // [m][c] roped q
__device__ __nv_bfloat16 g_Kr[MM*CC];      // [m][c] roped k (row-major)
__device__ __nv_bfloat16 g_Vbf[MM*CC];     // [m][c] v (row-major)
__device__ __nv_bfloat16 g_kv[128*DD*DD];  // [bh][d][e]
__device__ __nv_bfloat16 g_O16[MM*CC];     // attention output (pre-residual)

// ---------------------------------------------------------------------------
__global__ void init_invfreq_kernel() {
    int j = threadIdx.x;
    if (j < HALFC)
        g_invfreq[j] = (float)(1.0 / pow(10000.0, (double)(2 * j) / (double)CC));
}
__global__ __launch_bounds__(512) void init_rope_kernel() {
    int n = blockIdx.x;
    int j = threadIdx.x;
    float ang = (float)n * g_invfreq[j];
    float sv, cv;
    sincosf(ang, &sv, &cv);
    g_rope[n * HALFC + j] = make_float2(cv, sv);
}

// ---------------------------------------------------------------------------
__device__ __forceinline__ unsigned packbf2(float a, float b) {
    unsigned short lo = __bfloat16_as_ushort(__float2bfloat16(a));
    unsigned short hi = __bfloat16_as_ushort(__float2bfloat16(b));
    return (unsigned)lo | ((unsigned)hi << 16);
}

// Combined fp32->bf16 conversion: blocks 0..16383 -> x, then 1024 each for W0..W2
__global__ __launch_bounds__(256) void conv_all_kernel(
    const float* __restrict__ x, const float* __restrict__ W0,
    const float* __restrict__ W1, const float* __restrict__ W2)
{
    int blk = blockIdx.x;
    const float* __restrict__ src;
    __nv_bfloat16* __restrict__ dst;
    size_t base;
    if (blk < 16384) { src = x; dst = g_Abf; base = (size_t)blk * 256; }
    else {
        int w = (blk - 16384) >> 10;
        int bb = (blk - 16384) & 1023;
        src = (w == 0) ? W0 : (w == 1) ? W1 : W2;
        dst = g_Wbf[w];
        base = (size_t)bb * 256;
    }
    size_t i = base + threadIdx.x;
    float4 v = *(const float4*)(src + i * 4);
    uint2 u;
    u.x = packbf2(v.x, v.y); u.y = packbf2(v.z, v.w);
    *(uint2*)&dst[i * 4] = u;
}

// ---------------------------------------------------------------------------
// MMA helpers
__device__ __forceinline__ void ldsm4(unsigned* r, uint32_t addr) {
    asm volatile("ldmatrix.sync.aligned.m8n8.x4.shared.b16 {%0,%1,%2,%3},[%4];\n"
                 : "=r"(r[0]), "=r"(r[1]), "=r"(r[2]), "=r"(r[3]) : "r"(addr));
}
__device__ __forceinline__ void ldsm4t(unsigned* r, uint32_t addr) {
    asm volatile("ldmatrix.sync.aligned.m8n8.x4.trans.shared.b16 {%0,%1,%2,%3},[%4];\n"
                 : "=r"(r[0]), "=r"(r[1]), "=r"(r[2]), "=r"(r[3]) : "r"(addr));
}
__device__ __forceinline__ void mma16816(float* d, const unsigned* a, const unsigned* b) {
    asm volatile("mma.sync.aligned.m16n8k16.row.col.f32.bf16.bf16.f32 "
                 "{%0,%1,%2,%3},{%4,%5,%6,%7},{%8,%9},{%0,%1,%2,%3};\n"
                 : "+f"(d[0]), "+f"(d[1]), "+f"(d[2]), "+f"(d[3])
                 : "r"(a[0]), "r"(a[1]), "r"(a[2]), "r"(a[3]), "r"(b[0]), "r"(b[1]));
}
__device__ __forceinline__ void cp16(uint32_t sp, const void* gp) {
    asm volatile("cp.async.cg.shared.global [%0],[%1],16;\n" :: "r"(sp), "l"(gp));
}

// ---------------------------------------------------------------------------
// Main QKV GEMM. Tile 128x128, BK=64, 3-stage cp.async. blockIdx.z = which.
// Epilogue: all outputs row-major bf16 (coalesced); K adds rope + ksum.
#define SA 72
#define OPSZ (128 * SA * 2)
#define STGSZ (2 * OPSZ)
#define GEMM_SMEM (3 * STGSZ)      // 110592
#define NIT 16

__global__ __launch_bounds__(256, 2) void gemm_mma_kernel(
    const float* __restrict__ bq, const float* __restrict__ bk,
    const float* __restrict__ bv)
{
    extern __shared__ __nv_bfloat16 sm[];
    const int which = blockIdx.z;
    const float* __restrict__ bias = (which == 0) ? bq : (which == 1) ? bk : bv;
    const bool gel = (which < 2);
    const __nv_bfloat16* __restrict__ Wp = g_Wbf[which];

    const int t = threadIdx.x;
    const int lane = t & 31, warp = t >> 5;
    const int wm = warp & 3, wn = warp >> 2;
    const int m0 = blockIdx.y * 128, n0 = blockIdx.x * 128;

    const uint32_t sBase = (uint32_t)__cvta_generic_to_shared(sm);

    float acc[2][8][4];
    #pragma unroll
    for (int mt = 0; mt < 2; mt++)
        #pragma unroll
        for (int j = 0; j < 8; j++)
            #pragma unroll
            for (int r = 0; r < 4; r++) acc[mt][j][r] = 0.f;

    auto prefetch = [&](int it, int stg) {
        int kk = it << 6;
        uint32_t sA = sBase + stg * STGSZ;
        uint32_t sW = sA + OPSZ;
        #pragma unroll
        for (int i = 0; i < 8; i++) {
            int c = t + i * 256;
            int isW = c >> 10, cc = c & 1023;
            int row = cc >> 3, seg = cc & 7;
            const __nv_bfloat16* gp = isW
                ? Wp + (size_t)(n0 + row) * CC + kk + seg * 8
                : g_Abf + (size_t)(m0 + row) * CC + kk + seg * 8;
            cp16((isW ? sW : sA) + (row * SA + seg * 8) * 2, gp);
        }
        asm volatile("cp.async.commit_group;\n");
    };

    const int aRow = lane & 15, aCol = (lane >> 4) << 3;
    const int bRow = (lane & 7) + ((lane >> 4) << 3), bCol = ((lane >> 3) & 1) << 3;

    prefetch(0, 0);
    prefetch(1, 1);

    #pragma unroll 1
    for (int it = 0; it < NIT; ++it) {
        if (it < NIT - 1) asm volatile("cp.async.wait_group 1;\n");
        else              asm volatile("cp.async.wait_group 0;\n");
        __syncthreads();
        if (it + 2 < NIT) prefetch(it + 2, (it + 2) % 3);

        const uint32_t sA = sBase + (it % 3) * STGSZ;
        const uint32_t sW = sA + OPSZ;
        #pragma unroll
        for (int ks = 0; ks < 4; ++ks) {
            unsigned a[2][4], bf[4][4];
            #pragma unroll
            for (int mt = 0; mt < 2; ++mt)
                ldsm4(a[mt], sA + ((wm * 32 + mt * 16 + aRow) * SA + ks * 16 + aCol) * 2);
            #pragma unroll
            for (int np = 0; np < 4; ++np)
                ldsm4(bf[np], sW + ((wn * 64 + np * 16 + bRow) * SA + ks * 16 + bCol) * 2);
            #pragma unroll
            for (int mt = 0; mt < 2; ++mt)
                #pragma unroll
                for (int j = 0; j < 8; ++j)
                    mma16816(acc[mt][j], a[mt], &bf[j >> 1][(j & 1) * 2]);
        }
    }
    __syncthreads();     // smem free for epilogue staging

    const int gid = lane >> 2, tid2 = lane & 3;

    if (which == 0) {
        // Q: raw bf16 + roped bf16 row-major writes
        #pragma unroll
        for (int mt = 0; mt < 2; ++mt) {
            int rl = wm * 32 + mt * 16 + gid;
            int m_lo = m0 + rl, m_hi = m_lo + 8;
            int nlo = m_lo & 2047, nhi = m_hi & 2047;
            #pragma unroll
            for (int j = 0; j < 8; ++j) {
                int c = n0 + wn * 64 + j * 8 + tid2 * 2;
                float b0 = __ldg(&bias[c]), b1 = __ldg(&bias[c + 1]);
                float y0 = acc[mt][j][0] + b0, y1 = acc[mt][j][1] + b1;
                float y2 = acc[mt][j][2] + b0, y3 = acc[mt][j][3] + b1;
                y0 = 0.5f * y0 * (1.f + erff(y0 * 0.7071067811865476f)) + 0.21f;
                y1 = 0.5f * y1 * (1.f + erff(y1 * 0.7071067811865476f)) + 0.21f;
                y2 = 0.5f * y2 * (1.f + erff(y2 * 0.7071067811865476f)) + 0.21f;
                y3 = 0.5f * y3 * (1.f + erff(y3 * 0.7071067811865476f)) + 0.21f;
                *(unsigned*)&g_Qraw[(size_t)m_lo * CC + c] = packbf2(y0, y1);
                *(unsigned*)&g_Qraw[(size_t)m_hi * CC + c] = packbf2(y2, y3);
                float2 rlc = g_rope[nlo * HALFC + (c >> 1)];
                float2 rhc = g_rope[nhi * HALFC + (c >> 1)];
                *(unsigned*)&g_Qr[(size_t)m_lo * CC + c] =
                    packbf2(y0 * rlc.x - y1 * rlc.y, y1 * rlc.x + y0 * rlc.y);
                *(unsigned*)&g_Qr[(size_t)m_hi * CC + c] =
                    packbf2(y2 * rhc.x - y3 * rhc.y, y3 * rhc.x + y2 * rhc.y);
            }
        }
    } else {
        // K: bias+gelu+ksum+rope -> g_Kr row-major. V: bias -> g_Vbf row-major.
        float* ksmem = (float*)sm;                    // 4 x 128
        __nv_bfloat16* __restrict__ dst = gel ? g_Kr : g_Vbf;
        float ke[8], ko[8];
        #pragma unroll
        for (int j = 0; j < 8; ++j) { ke[j] = 0.f; ko[j] = 0.f; }

        #pragma unroll
        for (int mt = 0; mt < 2; ++mt) {
            int rl = wm * 32 + mt * 16 + gid;
            int m_lo = m0 + rl, m_hi = m_lo + 8;
            int nlo = m_lo & 2047, nhi = m_hi & 2047;
            #pragma unroll
            for (int j = 0; j < 8; ++j) {
                int c = n0 + wn * 64 + j * 8 + tid2 * 2;
                float b0 = __ldg(&bias[c]), b1 = __ldg(&bias[c + 1]);
                float y0 = acc[mt][j][0] + b0, y1 = acc[mt][j][1] + b1;
                float y2 = acc[mt][j][2] + b0, y3 = acc[mt][j][3] + b1;
                if (gel) {   // K path
                    y0 = 0.5f * y0 * (1.f + erff(y0 * 0.7071067811865476f)) + 0.21f;
                    y1 = 0.5f * y1 * (1.f + erff(y1 * 0.7071067811865476f)) + 0.21f;
                    y2 = 0.5f * y2 * (1.f + erff(y2 * 0.7071067811865476f)) + 0.21f;
                    y3 = 0.5f * y3 * (1.f + erff(y3 * 0.7071067811865476f)) + 0.21f;
                    ke[j] += y0 + y2;  ko[j] += y1 + y3;
                    float2 rlc = g_rope[nlo * HALFC + (c >> 1)];
                    float2 rhc = g_rope[nhi * HALFC + (c >> 1)];
                    float k0 = y0 * rlc.x - y1 * rlc.y, k1 = y1 * rlc.x + y0 * rlc.y;
                    float k2 = y2 * rhc.x - y3 * rhc.y, k3 = y3 * rhc.x + y2 * rhc.y;
                    y0 = k0; y1 = k1; y2 = k2; y3 = k3;
                }
                *(unsigned*)&dst[(size_t)m_lo * CC + c] = packbf2(y0, y1);
                *(unsigned*)&dst[(size_t)m_hi * CC + c] = packbf2(y2, y3);
            }
        }
        if (gel) {
            #pragma unroll
            for (int j = 0; j < 8; ++j) {
                float se = ke[j], so = ko[j];
                se += __shfl_down_sync(0xffffffffu, se, 4);
                se += __shfl_down_sync(0xffffffffu, se, 8);
                se += __shfl_down_sync(0xffffffffu, se, 16);
                so += __shfl_down_sync(0xffffffffu, so, 4);
                so += __shfl_down_sync(0xffffffffu, so, 8);
                so += __shfl_down_sync(0xffffffffu, so, 16);
                if (lane < 4) {
                    int lc = wn * 64 + j * 8 + tid2 * 2;
                    ksmem[wm * 128 + lc]     = se;
                    ksmem[wm * 128 + lc + 1] = so;
                }
            }
        }
        __syncthreads();
        if (gel && t < 128) {
            float s = ksmem[t] + ksmem[128 + t] + ksmem[256 + t] + ksmem[384 + t];
            g_kmp2[(size_t)blockIdx.y * CC + n0 + t] = s;
        }
    }
}

// ---------------------------------------------------------------------------
// kmean: reduce per-mblock partials, apply 1/N
__global__ __launch_bounds__(256) void kmean_kernel() {
    int b = blockIdx.x;
    for (int c = threadIdx.x; c < CC; c += 256) {
        float s = 0.f;
        #pragma unroll
        for (int mb = 0; mb < 16; mb++)
            s += g_kmp2[(size_t)(b * 16 + mb) * CC + c];
        g_km[b * CC + c] = s * (1.f / (float)NN);
    }
}

// ---------------------------------------------------------------------------
// kv[d][e] = (1/N) sum_n Kr[n,d] * V[n,e]  via trans-ldmatrix fragments.
// Tiles are row-major [n][64] slices of g_Kr/g_Vbf; output stored [d][e].
#define KSA 72
#define KVOP (64 * KSA * 2)            // 9216 per operand per stage
#define KVSTG (2 * KVOP)               // 18432
#define KV_SMEM (3 * KVSTG)            // 55296
__global__ __launch_bounds__(128) void kv_mma_kernel() {
    extern __shared__ __nv_bfloat16 ksm[];
    int bh = blockIdx.x;
    int h = bh & 15, b = bh >> 4;
    int t = threadIdx.x, lane = t & 31, warp = t >> 5;
    const __nv_bfloat16* Ap = g_Kr + (size_t)b * NN * CC + h * 64;
    const __nv_bfloat16* Bp = g_Vbf + (size_t)b * NN * CC + h * 64;
    const uint32_t s0 = (uint32_t)__cvta_generic_to_shared(ksm);

    float acc[8][4];
    #pragma unroll
    for (int j = 0; j < 8; j++)
        #pragma unroll
        for (int r = 0; r < 4; r++) acc[j][r] = 0.f;

    auto pf = [&](int it, int stg) {
        int nn = it * 64;
        uint32_t sa = s0 + stg * KVSTG;
        uint32_t sb = sa + KVOP;
        #pragma unroll
        for (int i = 0; i < 4; i++) {
            int ii = t + i * 128;
            int row = ii >> 3, seg = ii & 7;       // row = n-local, 8 segs of 16B
            cp16(sa + (row * KSA + seg * 8) * 2, Ap + (size_t)(nn + row) * CC + seg * 8);
            cp16(sb + (row * KSA + seg * 8) * 2, Bp + (size_t)(nn + row) * CC + seg * 8);
        }
        asm volatile("cp.async.commit_group;\n");
    };
    // trans-A fragment lanes: row(k=n) = (lane&7)+((lane>>4)<<3), col(m=d) = ((lane>>3)&1)<<3
    const int atRow = (lane & 7) + ((lane >> 4) << 3), atCol = ((lane >> 3) & 1) << 3;
    // trans-B fragment lanes: row(k=n) = (lane&7)+(((lane>>3)&1)<<3), col(n=e) = (lane>>4)<<3
    const int btRow = (lane & 7) + (((lane >> 3) & 1) << 3), btCol = (lane >> 4) << 3;

    pf(0, 0);
    pf(1, 1);
    #pragma unroll 1
    for (int it = 0; it < 32; ++it) {
        if (it < 31) asm volatile("cp.async.wait_group 1;\n");
        else         asm volatile("cp.async.wait_group 0;\n");
        __syncthreads();
        if (it + 2 < 32) pf(it + 2, (it + 2) % 3);
        const uint32_t sa = s0 + (it % 3) * KVSTG;
        const uint32_t sb = sa + KVOP;
        #pragma unroll
        for (int ks = 0; ks < 4; ++ks) {           // ks: 16-n chunks within 64
            unsigned a[4], bf[4][4];
            ldsm4t(a, sa + ((ks * 16 + atRow) * KSA + warp * 16 + atCol) * 2);
            #pragma unroll
            for (int np = 0; np < 4; ++np)
                ldsm4t(bf[np], sb + ((ks * 16 + btRow) * KSA + np * 16 + btCol) * 2);
            #pragma unroll
            for (int j = 0; j < 8; ++j)
                mma16816(acc[j], a, &bf[j >> 1][(j & 1) * 2]);
        }
    }
    // epilogue: scale 1/N, store [d][e] row-major directly
    const int gid = lane >> 2, tid2 = lane & 3;
    const float sc = 1.f / (float)NN;
    int d_lo = warp * 16 + gid, d_hi = d_lo + 8;
    #pragma unroll
    for (int j = 0; j < 8; ++j) {
        int e = j * 8 + tid2 * 2;
        *(unsigned*)&g_kv[(size_t)bh * 4096 + d_lo * 64 + e] =
            packbf2(acc[j][0] * sc, acc[j][1] * sc);
        *(unsigned*)&g_kv[(size_t)bh * 4096 + d_hi * 64 + e] =
            packbf2(acc[j][2] * sc, acc[j][3] * sc);
    }
}

// ---------------------------------------------------------------------------
// out[m][h*64+e] = z[m,h] * sum_d Qr[m][h*64+d] * kv[d][e]  (z fused in)
__global__ __launch_bounds__(256) void out_mma_kernel() {
    int bh = blockIdx.x;
    int h = bh & 15, b = bh >> 4;
    int m0 = b * NN + blockIdx.y * 128;
    __shared__ __align__(16) __nv_bfloat16 sA[128 * 72];
    __shared__ __align__(16) __nv_bfloat16 sB[64 * 72];
    __shared__ float kms[64];
    __shared__ float zv[128];
    int t = threadIdx.x, lane = t & 31, warp = t >> 5;
    const uint32_t a0 = (uint32_t)__cvta_generic_to_shared(sA);
    const uint32_t b0 = (uint32_t)__cvta_generic_to_shared(sB);

    #pragma unroll
    for (int i = 0; i < 4; i++) {     // A: 128 rows x 8 segs
        int ii = t + i * 256;
        int row = ii >> 3, seg = ii & 7;
        cp16(a0 + (row * 72 + seg * 8) * 2,
             g_Qr + (size_t)(m0 + row) * CC + h * 64 + seg * 8);
    }
    #pragma unroll
    for (int i = 0; i < 2; i++) {     // B: kv [d][e] 64 rows x 8 segs
        int ii = t + i * 256;
        int row = ii >> 3, seg = ii & 7;
        cp16(b0 + (row * 72 + seg * 8) * 2,
             g_kv + (size_t)bh * 4096 + row * 64 + seg * 8);
    }
    asm volatile("cp.async.commit_group;\n");

    // z computation in cp.async shadow
    if (t < 64) kms[t] = g_km[b * CC + h * 64 + t];
    __syncthreads();
    if (t < 128) {
        const __nv_bfloat16* qp = g_Qraw + (size_t)(m0 + t) * CC + h * 64;
        float s = 0.f;
        #pragma unroll
        for (int i = 0; i < 8; i++) {
            uint4 v = *(const uint4*)(qp + i * 8);
            unsigned u[4] = {v.x, v.y, v.z, v.w};
            #pragma unroll
            for (int k = 0; k < 4; k++) {
                float lo = __bfloat162float(__ushort_as_bfloat16((unsigned short)(u[k] & 0xffff)));
                float hi = __bfloat162float(__ushort_as_bfloat16((unsigned short)(u[k] >> 16)));
                s += lo * kms[i * 8 + k * 2] + hi * kms[i * 8 + k * 2 + 1];
            }
        }
        zv[t] = 1.f / (s + 1e-6f);
    }
    asm volatile("cp.async.wait_group 0;\n");
    __syncthreads();

    const int aRow = lane & 15, aCol = (lane >> 4) << 3;
    // trans-B: row(k=d) = (lane&7)+(((lane>>3)&1)<<3), col(n=e) = (lane>>4)<<3
    const int btRow = (lane & 7) + (((lane >> 3) & 1) << 3), btCol = (lane >> 4) << 3;
    float acc[8][4];
    #pragma unroll
    for (int j = 0; j < 8; j++)
        #pragma unroll
        for (int r = 0; r < 4; r++) acc[j][r] = 0.f;

    #pragma unroll
    for (int ks = 0; ks < 4; ++ks) {
        unsigned a[4], bf[4][4];
        ldsm4(a, a0 + ((warp * 16 + aRow) * 72 + ks * 16 + aCol) * 2);
        #pragma unroll
        for (int np = 0; np < 4; ++np)
            ldsm4t(bf[np], b0 + ((ks * 16 + btRow) * 72 + np * 16 + btCol) * 2);
        #pragma unroll
        for (int j = 0; j < 8; ++j)
            mma16816(acc[j], a, &bf[j >> 1][(j & 1) * 2]);
    }

    const int gid = lane >> 2, tid2 = lane & 3;
    int rl = warp * 16 + gid;
    int m_lo = m0 + rl, m_hi = m_lo + 8;
    float zl = zv[rl], zh = zv[rl + 8];
    #pragma unroll
    for (int j = 0; j < 8; ++j) {
        int c = h * 64 + j * 8 + tid2 * 2;
        *(unsigned*)&g_O16[(size_t)m_lo * CC + c] = packbf2(acc[j][0] * zl, acc[j][1] * zl);
        *(unsigned*)&g_O16[(size_t)m_hi * CC + c] = packbf2(acc[j][2] * zh, acc[j][3] * zh);
    }
}

// ---------------------------------------------------------------------------
__global__ __launch_bounds__(256) void ln_kernel(
    const float* __restrict__ x, const float* __restrict__ gamma,
    const float* __restrict__ beta, float* __restrict__ out)
{
    int row = blockIdx.x;
    int t = threadIdx.x;
    uint2 ou = *(const uint2*)&g_O16[(size_t)row * CC + t * 4];
    float4 xv = *(const float4*)&x[(size_t)row * CC + t * 4];
    float4 r;
    r.x = xv.x + __bfloat162float(__ushort_as_bfloat16((unsigned short)(ou.x & 0xffff)));
    r.y = xv.y + __bfloat162float(__ushort_as_bfloat16((unsigned short)(ou.x >> 16)));
    r.z = xv.z + __bfloat162float(__ushort_as_bfloat16((unsigned short)(ou.y & 0xffff)));
    r.w = xv.w + __bfloat162float(__ushort_as_bfloat16((unsigned short)(ou.y >> 16)));
    float s  = r.x + r.y + r.z + r.w;
    float sq = r.x * r.x + r.y * r.y + r.z * r.z + r.w * r.w;
    #pragma unroll
    for (int off = 16; off; off >>= 1) {
        s  += __shfl_xor_sync(0xffffffffu, s, off);
        sq += __shfl_xor_sync(0xffffffffu, sq, off);
    }
    __shared__ float ss[8], ssq[8];
    __shared__ float mean_s, rstd_s;
    int w = t >> 5, lane = t & 31;
    if (lane == 0) { ss[w] = s; ssq[w] = sq; }
    __syncthreads();
    if (t == 0) {
        float S = 0.f, SQ = 0.f;
        #pragma unroll
        for (int i = 0; i < 8; i++) { S += ss[i]; SQ += ssq[i]; }
        float mean = S * (1.f / (float)CC);
        float var  = SQ * (1.f / (float)CC) - mean * mean;
        mean_s = mean;
        rstd_s = rsqrtf(var + 1e-12f);
    }
    __syncthreads();
    float mean = mean_s, rstd = rstd_s;
    float4 g  = *(const float4*)&gamma[t * 4];
    float4 be = *(const float4*)&beta[t * 4];
    float4 o;
    o.x = (r.x - mean) * rstd * g.x + be.x;
    o.y = (r.y - mean) * rstd * g.y + be.y;
    o.z = (r.z - mean) * rstd * g.z + be.z;
    o.w = (r.w - mean) * rstd * g.w + be.w;
    *(float4*)&out[(size_t)row * CC + t * 4] = o;
}

// ---------------------------------------------------------------------------
extern "C" void kernel_launch(void* const* d_in, const int* in_sizes, int n_in,
                              void* d_out, int out_size) {
    const float* x     = (const float*)d_in[0];
    const float* Wq    = (const float*)d_in[1];
    const float* bq    = (const float*)d_in[2];
    const float* Wk    = (const float*)d_in[3];
    const float* bk    = (const float*)d_in[4];
    const float* Wv    = (const float*)d_in[5];
    const float* bv    = (const float*)d_in[6];
    const float* gamma = (const float*)d_in[7];
    const float* beta  = (const float*)d_in[8];
    float* out = (float*)d_out;

    init_invfreq_kernel<<<1, 512>>>();
    init_rope_kernel<<<NN, 512>>>();
    conv_all_kernel<<<16384 + 3 * 1024, 256>>>(x, Wq, Wk, Wv);

    cudaFuncSetAttribute(gemm_mma_kernel,
                         cudaFuncAttributeMaxDynamicSharedMemorySize, GEMM_SMEM);
    dim3 ggrid(CC / 128, MM / 128, 3);
    gemm_mma_kernel<<<ggrid, 256, GEMM_SMEM>>>(bq, bk, bv);   // 4th launch -> profiled

    kmean_kernel<<<BB, 256>>>();
    cudaFuncSetAttribute(kv_mma_kernel,
                         cudaFuncAttributeMaxDynamicSharedMemorySize, KV_SMEM);
    kv_mma_kernel<<<128, 128, KV_SMEM>>>();
    out_mma_kernel<<<dim3(128, NN / 128), 256>>>();
    ln_kernel<<<MM, 256>>>(x, gamma, beta, out);
}

// round 11
// speedup vs baseline: 2.8096x; 1.0103x over previous
#include <cuda_runtime.h>
#include <cuda_bf16.h>
#include <math.h>
#include <stdint.h>

// Problem constants
#define BB 8
#define NN 2048
#define CC 1024
#define HH 16
#define DD 64
#define MM (BB*NN)        // 16384 rows
#define HALFC (CC/2)

// Scratch (device globals: allocation-free per harness rules)
__device__ float  g_kmp2[128*CC];          // per-mblock raw-K column sums
__device__ float  g_km[128*DD];            // [b][c] k-mean (includes 1/N)
__device__ float  g_invfreq[HALFC];
__device__ float2 g_rope[NN*HALFC];        // (cos, sin)

// bf16 operands
__device__ __nv_bfloat16 g_Abf[MM*CC];
__device__ __nv_bfloat16 g_Wbf[3][CC*CC];
__device__ __nv_bfloat16 g_Qraw[MM*CC];    // [m][c] post-gelu raw q (for z)
__device__ __nv_bfloat16 g_Qr[MM*CC];      // [m][c] roped q
__device__ __nv_bfloat16 g_Kr[MM*CC];      // [m][c] roped k (row-major)
__device__ __nv_bfloat16 g_Vbf[MM*CC];     // [m][c] v (row-major)
__device__ __nv_bfloat16 g_kv[128*DD*DD];  // [bh][d][e]
__device__ __nv_bfloat16 g_O16[MM*CC];     // attention output (pre-residual)

// ---------------------------------------------------------------------------
__global__ void init_invfreq_kernel() {
    int j = threadIdx.x;
    if (j < HALFC)
        g_invfreq[j] = (float)(1.0 / pow(10000.0, (double)(2 * j) / (double)CC));
}
__global__ __launch_bounds__(512) void init_rope_kernel() {
    int n = blockIdx.x;
    int j = threadIdx.x;
    float ang = (float)n * g_invfreq[j];
    float sv, cv;
    sincosf(ang, &sv, &cv);
    g_rope[n * HALFC + j] = make_float2(cv, sv);
}

// ---------------------------------------------------------------------------
__device__ __forceinline__ unsigned packbf2(float a, float b) {
    unsigned short lo = __bfloat16_as_ushort(__float2bfloat16(a));
    unsigned short hi = __bfloat16_as_ushort(__float2bfloat16(b));
    return (unsigned)lo | ((unsigned)hi << 16);
}

// Grid-stride fp32->bf16 conversion; W loop converts all three per index (MLP).
#define CONV_BLOCKS 1184
__global__ __launch_bounds__(256) void conv_all_kernel(
    const float* __restrict__ x, const float* __restrict__ W0,
    const float* __restrict__ W1, const float* __restrict__ W2)
{
    const int T = CONV_BLOCKS * 256;
    int tid = blockIdx.x * 256 + threadIdx.x;
    const int NX4 = MM * CC / 4;
    const int NW4 = CC * CC / 4;
    for (int i = tid; i < NX4; i += T) {
        float4 v = __ldg((const float4*)x + i);
        uint2 u; u.x = packbf2(v.x, v.y); u.y = packbf2(v.z, v.w);
        *((uint2*)g_Abf + i) = u;
    }
    for (int i = tid; i < NW4; i += T) {
        float4 v0 = __ldg((const float4*)W0 + i);
        float4 v1 = __ldg((const float4*)W1 + i);
        float4 v2 = __ldg((const float4*)W2 + i);
        uint2 u0, u1, u2;
        u0.x = packbf2(v0.x, v0.y); u0.y = packbf2(v0.z, v0.w);
        u1.x = packbf2(v1.x, v1.y); u1.y = packbf2(v1.z, v1.w);
        u2.x = packbf2(v2.x, v2.y); u2.y = packbf2(v2.z, v2.w);
        *((uint2*)g_Wbf[0] + i) = u0;
        *((uint2*)g_Wbf[1] + i) = u1;
        *((uint2*)g_Wbf[2] + i) = u2;
    }
}

// ---------------------------------------------------------------------------
// MMA helpers
__device__ __forceinline__ void ldsm4(unsigned* r, uint32_t addr) {
    asm volatile("ldmatrix.sync.aligned.m8n8.x4.shared.b16 {%0,%1,%2,%3},[%4];\n"
                 : "=r"(r[0]), "=r"(r[1]), "=r"(r[2]), "=r"(r[3]) : "r"(addr));
}
__device__ __forceinline__ void ldsm4t(unsigned* r, uint32_t addr) {
    asm volatile("ldmatrix.sync.aligned.m8n8.x4.trans.shared.b16 {%0,%1,%2,%3},[%4];\n"
                 : "=r"(r[0]), "=r"(r[1]), "=r"(r[2]), "=r"(r[3]) : "r"(addr));
}
__device__ __forceinline__ void mma16816(float* d, const unsigned* a, const unsigned* b) {
    asm volatile("mma.sync.aligned.m16n8k16.row.col.f32.bf16.bf16.f32 "
                 "{%0,%1,%2,%3},{%4,%5,%6,%7},{%8,%9},{%0,%1,%2,%3};\n"
                 : "+f"(d[0]), "+f"(d[1]), "+f"(d[2]), "+f"(d[3])
                 : "r"(a[0]), "r"(a[1]), "r"(a[2]), "r"(a[3]), "r"(b[0]), "r"(b[1]));
}
__device__ __forceinline__ void cp16(uint32_t sp, const void* gp) {
    asm volatile("cp.async.cg.shared.global [%0],[%1],16;\n" :: "r"(sp), "l"(gp));
}

// ---------------------------------------------------------------------------
// Main QKV GEMM. Tile 128x128, BK=64, 3-stage cp.async. blockIdx.z = which.
#define SA 72
#define OPSZ (128 * SA * 2)
#define STGSZ (2 * OPSZ)
#define GEMM_SMEM (3 * STGSZ)      // 110592
#define NIT 16

__global__ __launch_bounds__(256, 2) void gemm_mma_kernel(
    const float* __restrict__ bq, const float* __restrict__ bk,
    const float* __restrict__ bv)
{
    extern __shared__ __nv_bfloat16 sm[];
    const int which = blockIdx.z;
    const float* __restrict__ bias = (which == 0) ? bq : (which == 1) ? bk : bv;
    const bool gel = (which < 2);
    const __nv_bfloat16* __restrict__ Wp = g_Wbf[which];

    const int t = threadIdx.x;
    const int lane = t & 31, warp = t >> 5;
    const int wm = warp & 3, wn = warp >> 2;
    const int m0 = blockIdx.y * 128, n0 = blockIdx.x * 128;

    const uint32_t sBase = (uint32_t)__cvta_generic_to_shared(sm);

    float acc[2][8][4];
    #pragma unroll
    for (int mt = 0; mt < 2; mt++)
        #pragma unroll
        for (int j = 0; j < 8; j++)
            #pragma unroll
            for (int r = 0; r < 4; r++) acc[mt][j][r] = 0.f;

    auto prefetch = [&](int it, int stg) {
        int kk = it << 6;
        uint32_t sA = sBase + stg * STGSZ;
        uint32_t sW = sA + OPSZ;
        #pragma unroll
        for (int i = 0; i < 8; i++) {
            int c = t + i * 256;
            int isW = c >> 10, cc = c & 1023;
            int row = cc >> 3, seg = cc & 7;
            const __nv_bfloat16* gp = isW
                ? Wp + (size_t)(n0 + row) * CC + kk + seg * 8
                : g_Abf + (size_t)(m0 + row) * CC + kk + seg * 8;
            cp16((isW ? sW : sA) + (row * SA + seg * 8) * 2, gp);
        }
        asm volatile("cp.async.commit_group;\n");
    };

    const int aRow = lane & 15, aCol = (lane >> 4) << 3;
    const int bRow = (lane & 7) + ((lane >> 4) << 3), bCol = ((lane >> 3) & 1) << 3;

    prefetch(0, 0);
    prefetch(1, 1);

    #pragma unroll 1
    for (int it = 0; it < NIT; ++it) {
        if (it < NIT - 1) asm volatile("cp.async.wait_group 1;\n");
        else              asm volatile("cp.async.wait_group 0;\n");
        __syncthreads();
        if (it + 2 < NIT) prefetch(it + 2, (it + 2) % 3);

        const uint32_t sA = sBase + (it % 3) * STGSZ;
        const uint32_t sW = sA + OPSZ;
        #pragma unroll
        for (int ks = 0; ks < 4; ++ks) {
            unsigned a[2][4], bf[4][4];
            #pragma unroll
            for (int mt = 0; mt < 2; ++mt)
                ldsm4(a[mt], sA + ((wm * 32 + mt * 16 + aRow) * SA + ks * 16 + aCol) * 2);
            #pragma unroll
            for (int np = 0; np < 4; ++np)
                ldsm4(bf[np], sW + ((wn * 64 + np * 16 + bRow) * SA + ks * 16 + bCol) * 2);
            #pragma unroll
            for (int mt = 0; mt < 2; ++mt)
                #pragma unroll
                for (int j = 0; j < 8; ++j)
                    mma16816(acc[mt][j], a[mt], &bf[j >> 1][(j & 1) * 2]);
        }
    }
    __syncthreads();     // smem free for epilogue staging

    const int gid = lane >> 2, tid2 = lane & 3;

    if (which == 0) {
        // Q: raw bf16 + roped bf16 row-major writes
        #pragma unroll
        for (int mt = 0; mt < 2; ++mt) {
            int rl = wm * 32 + mt * 16 + gid;
            int m_lo = m0 + rl, m_hi = m_lo + 8;
            int nlo = m_lo & 2047, nhi = m_hi & 2047;
            #pragma unroll
            for (int j = 0; j < 8; ++j) {
                int c = n0 + wn * 64 + j * 8 + tid2 * 2;
                float b0 = __ldg(&bias[c]), b1 = __ldg(&bias[c + 1]);
                float y0 = acc[mt][j][0] + b0, y1 = acc[mt][j][1] + b1;
                float y2 = acc[mt][j][2] + b0, y3 = acc[mt][j][3] + b1;
                y0 = 0.5f * y0 * (1.f + erff(y0 * 0.7071067811865476f)) + 0.21f;
                y1 = 0.5f * y1 * (1.f + erff(y1 * 0.7071067811865476f)) + 0.21f;
                y2 = 0.5f * y2 * (1.f + erff(y2 * 0.7071067811865476f)) + 0.21f;
                y3 = 0.5f * y3 * (1.f + erff(y3 * 0.7071067811865476f)) + 0.21f;
                *(unsigned*)&g_Qraw[(size_t)m_lo * CC + c] = packbf2(y0, y1);
                *(unsigned*)&g_Qraw[(size_t)m_hi * CC + c] = packbf2(y2, y3);
                float2 rlc = g_rope[nlo * HALFC + (c >> 1)];
                float2 rhc = g_rope[nhi * HALFC + (c >> 1)];
                *(unsigned*)&g_Qr[(size_t)m_lo * CC + c] =
                    packbf2(y0 * rlc.x - y1 * rlc.y, y1 * rlc.x + y0 * rlc.y);
                *(unsigned*)&g_Qr[(size_t)m_hi * CC + c] =
                    packbf2(y2 * rhc.x - y3 * rhc.y, y3 * rhc.x + y2 * rhc.y);
            }
        }
    } else {
        // K: bias+gelu+ksum+rope -> g_Kr row-major. V: bias -> g_Vbf row-major.
        float* ksmem = (float*)sm;                    // 4 x 128
        __nv_bfloat16* __restrict__ dst = gel ? g_Kr : g_Vbf;
        float ke[8], ko[8];
        #pragma unroll
        for (int j = 0; j < 8; ++j) { ke[j] = 0.f; ko[j] = 0.f; }

        #pragma unroll
        for (int mt = 0; mt < 2; ++mt) {
            int rl = wm * 32 + mt * 16 + gid;
            int m_lo = m0 + rl, m_hi = m_lo + 8;
            int nlo = m_lo & 2047, nhi = m_hi & 2047;
            #pragma unroll
            for (int j = 0; j < 8; ++j) {
                int c = n0 + wn * 64 + j * 8 + tid2 * 2;
                float b0 = __ldg(&bias[c]), b1 = __ldg(&bias[c + 1]);
                float y0 = acc[mt][j][0] + b0, y1 = acc[mt][j][1] + b1;
                float y2 = acc[mt][j][2] + b0, y3 = acc[mt][j][3] + b1;
                if (gel) {   // K path
                    y0 = 0.5f * y0 * (1.f + erff(y0 * 0.7071067811865476f)) + 0.21f;
                    y1 = 0.5f * y1 * (1.f + erff(y1 * 0.7071067811865476f)) + 0.21f;
                    y2 = 0.5f * y2 * (1.f + erff(y2 * 0.7071067811865476f)) + 0.21f;
                    y3 = 0.5f * y3 * (1.f + erff(y3 * 0.7071067811865476f)) + 0.21f;
                    ke[j] += y0 + y2;  ko[j] += y1 + y3;
                    float2 rlc = g_rope[nlo * HALFC + (c >> 1)];
                    float2 rhc = g_rope[nhi * HALFC + (c >> 1)];
                    float k0 = y0 * rlc.x - y1 * rlc.y, k1 = y1 * rlc.x + y0 * rlc.y;
                    float k2 = y2 * rhc.x - y3 * rhc.y, k3 = y3 * rhc.x + y2 * rhc.y;
                    y0 = k0; y1 = k1; y2 = k2; y3 = k3;
                }
                *(unsigned*)&dst[(size_t)m_lo * CC + c] = packbf2(y0, y1);
                *(unsigned*)&dst[(size_t)m_hi * CC + c] = packbf2(y2, y3);
            }
        }
        if (gel) {
            #pragma unroll
            for (int j = 0; j < 8; ++j) {
                float se = ke[j], so = ko[j];
                se += __shfl_down_sync(0xffffffffu, se, 4);
                se += __shfl_down_sync(0xffffffffu, se, 8);
                se += __shfl_down_sync(0xffffffffu, se, 16);
                so += __shfl_down_sync(0xffffffffu, so, 4);
                so += __shfl_down_sync(0xffffffffu, so, 8);
                so += __shfl_down_sync(0xffffffffu, so, 16);
                if (lane < 4) {
                    int lc = wn * 64 + j * 8 + tid2 * 2;
                    ksmem[wm * 128 + lc]     = se;
                    ksmem[wm * 128 + lc + 1] = so;
                }
            }
        }
        __syncthreads();
        if (gel && t < 128) {
            float s = ksmem[t] + ksmem[128 + t] + ksmem[256 + t] + ksmem[384 + t];
            g_kmp2[(size_t)blockIdx.y * CC + n0 + t] = s;
        }
    }
}

// ---------------------------------------------------------------------------
// kmean: reduce per-mblock partials, apply 1/N
__global__ __launch_bounds__(256) void kmean_kernel() {
    int b = blockIdx.x;
    for (int c = threadIdx.x; c < CC; c += 256) {
        float s = 0.f;
        #pragma unroll
        for (int mb = 0; mb < 16; mb++)
            s += g_kmp2[(size_t)(b * 16 + mb) * CC + c];
        g_km[b * CC + c] = s * (1.f / (float)NN);
    }
}

// ---------------------------------------------------------------------------
// kv[d][e] = (1/N) sum_n Kr[n,d] * V[n,e]  via trans-ldmatrix fragments.
// 256 threads: two warp-groups, each handles half the sequence (split-N),
// each with its own 3-stage pipeline; smem reduce at the end.
#define KSA 72
#define KVOP (64 * KSA * 2)            // 9216 per operand per stage
#define KVSTG (2 * KVOP)               // 18432
#define KV_SMEM (6 * KVSTG)            // 110592 (3 stages x 2 groups)
__global__ __launch_bounds__(256) void kv_mma_kernel() {
    extern __shared__ __nv_bfloat16 ksm[];
    int bh = blockIdx.x;
    int h = bh & 15, b = bh >> 4;
    int t = threadIdx.x, lane = t & 31, warp = t >> 5;
    int grp = warp >> 2, wi = warp & 3;           // group 0/1, warp-in-group
    const __nv_bfloat16* Ap = g_Kr + (size_t)b * NN * CC + (size_t)grp * 1024 * CC + h * 64;
    const __nv_bfloat16* Bp = g_Vbf + (size_t)b * NN * CC + (size_t)grp * 1024 * CC + h * 64;
    const uint32_t s0 = (uint32_t)__cvta_generic_to_shared(ksm) + grp * 3 * KVSTG;
    int gt = t & 127;                              // thread-in-group

    float acc[8][4];
    #pragma unroll
    for (int j = 0; j < 8; j++)
        #pragma unroll
        for (int r = 0; r < 4; r++) acc[j][r] = 0.f;

    auto pf = [&](int it, int stg) {
        int nn = it * 64;
        uint32_t sa = s0 + stg * KVSTG;
        uint32_t sb = sa + KVOP;
        #pragma unroll
        for (int i = 0; i < 4; i++) {
            int ii = gt + i * 128;
            int row = ii >> 3, seg = ii & 7;
            cp16(sa + (row * KSA + seg * 8) * 2, Ap + (size_t)(nn + row) * CC + seg * 8);
            cp16(sb + (row * KSA + seg * 8) * 2, Bp + (size_t)(nn + row) * CC + seg * 8);
        }
        asm volatile("cp.async.commit_group;\n");
    };
    const int atRow = (lane & 7) + ((lane >> 4) << 3), atCol = ((lane >> 3) & 1) << 3;
    const int btRow = (lane & 7) + (((lane >> 3) & 1) << 3), btCol = (lane >> 4) << 3;

    pf(0, 0);
    pf(1, 1);
    #pragma unroll 1
    for (int it = 0; it < 16; ++it) {
        if (it < 15) asm volatile("cp.async.wait_group 1;\n");
        else         asm volatile("cp.async.wait_group 0;\n");
        __syncthreads();
        if (it + 2 < 16) pf(it + 2, (it + 2) % 3);
        const uint32_t sa = s0 + (it % 3) * KVSTG;
        const uint32_t sb = sa + KVOP;
        #pragma unroll
        for (int ks = 0; ks < 4; ++ks) {           // ks: 16-n chunks within 64
            unsigned a[4], bf[4][4];
            ldsm4t(a, sa + ((ks * 16 + atRow) * KSA + wi * 16 + atCol) * 2);
            #pragma unroll
            for (int np = 0; np < 4; ++np)
                ldsm4t(bf[np], sb + ((ks * 16 + btRow) * KSA + np * 16 + btCol) * 2);
            #pragma unroll
            for (int j = 0; j < 8; ++j)
                mma16816(acc[j], a, &bf[j >> 1][(j & 1) * 2]);
        }
    }
    __syncthreads();
    // reduce: group 1 stores acc to smem, group 0 adds and writes
    float* red = (float*)ksm;      // 64 x 64 fp32 = 16 KB
    const int gid = lane >> 2, tid2 = lane & 3;
    int d_lo = wi * 16 + gid, d_hi = d_lo + 8;
    if (grp == 1) {
        #pragma unroll
        for (int j = 0; j < 8; ++j) {
            int e = j * 8 + tid2 * 2;
            red[d_lo * 64 + e]     = acc[j][0];
            red[d_lo * 64 + e + 1] = acc[j][1];
            red[d_hi * 64 + e]     = acc[j][2];
            red[d_hi * 64 + e + 1] = acc[j][3];
        }
    }
    __syncthreads();
    if (grp == 0) {
        const float sc = 1.f / (float)NN;
        #pragma unroll
        for (int j = 0; j < 8; ++j) {
            int e = j * 8 + tid2 * 2;
            *(unsigned*)&g_kv[(size_t)bh * 4096 + d_lo * 64 + e] =
                packbf2((acc[j][0] + red[d_lo * 64 + e]) * sc,
                        (acc[j][1] + red[d_lo * 64 + e + 1]) * sc);
            *(unsigned*)&g_kv[(size_t)bh * 4096 + d_hi * 64 + e] =
                packbf2((acc[j][2] + red[d_hi * 64 + e]) * sc,
                        (acc[j][3] + red[d_hi * 64 + e + 1]) * sc);
        }
    }
}

// ---------------------------------------------------------------------------
// out[m][h*64+e] = z[m,h] * sum_d Qr[m][h*64+d] * kv[d][e]  (z fused in)
__global__ __launch_bounds__(256) void out_mma_kernel() {
    int bh = blockIdx.x;
    int h = bh & 15, b = bh >> 4;
    int m0 = b * NN + blockIdx.y * 128;
    __shared__ __align__(16) __nv_bfloat16 sA[128 * 72];
    __shared__ __align__(16) __nv_bfloat16 sB[64 * 72];
    __shared__ float kms[64];
    __shared__ float zv[128];
    int t = threadIdx.x, lane = t & 31, warp = t >> 5;
    const uint32_t a0 = (uint32_t)__cvta_generic_to_shared(sA);
    const uint32_t b0 = (uint32_t)__cvta_generic_to_shared(sB);

    #pragma unroll
    for (int i = 0; i < 4; i++) {     // A: 128 rows x 8 segs
        int ii = t + i * 256;
        int row = ii >> 3, seg = ii & 7;
        cp16(a0 + (row * 72 + seg * 8) * 2,
             g_Qr + (size_t)(m0 + row) * CC + h * 64 + seg * 8);
    }
    #pragma unroll
    for (int i = 0; i < 2; i++) {     // B: kv [d][e] 64 rows x 8 segs
        int ii = t + i * 256;
        int row = ii >> 3, seg = ii & 7;
        cp16(b0 + (row * 72 + seg * 8) * 2,
             g_kv + (size_t)bh * 4096 + row * 64 + seg * 8);
    }
    asm volatile("cp.async.commit_group;\n");

    // z computation in cp.async shadow
    if (t < 64) kms[t] = g_km[b * CC + h * 64 + t];
    __syncthreads();
    if (t < 128) {
        const __nv_bfloat16* qp = g_Qraw + (size_t)(m0 + t) * CC + h * 64;
        float s = 0.f;
        #pragma unroll
        for (int i = 0; i < 8; i++) {
            uint4 v = *(const uint4*)(qp + i * 8);
            unsigned u[4] = {v.x, v.y, v.z, v.w};
            #pragma unroll
            for (int k = 0; k < 4; k++) {
                float lo = __bfloat162float(__ushort_as_bfloat16((unsigned short)(u[k] & 0xffff)));
                float hi = __bfloat162float(__ushort_as_bfloat16((unsigned short)(u[k] >> 16)));
                s += lo * kms[i * 8 + k * 2] + hi * kms[i * 8 + k * 2 + 1];
            }
        }
        zv[t] = 1.f / (s + 1e-6f);
    }
    asm volatile("cp.async.wait_group 0;\n");
    __syncthreads();

    const int aRow = lane & 15, aCol = (lane >> 4) << 3;
    const int btRow = (lane & 7) + (((lane >> 3) & 1) << 3), btCol = (lane >> 4) << 3;
    float acc[8][4];
    #pragma unroll
    for (int j = 0; j < 8; j++)
        #pragma unroll
        for (int r = 0; r < 4; r++) acc[j][r] = 0.f;

    #pragma unroll
    for (int ks = 0; ks < 4; ++ks) {
        unsigned a[4], bf[4][4];
        ldsm4(a, a0 + ((warp * 16 + aRow) * 72 + ks * 16 + aCol) * 2);
        #pragma unroll
        for (int np = 0; np < 4; ++np)
            ldsm4t(bf[np], b0 + ((ks * 16 + btRow) * 72 + np * 16 + btCol) * 2);
        #pragma unroll
        for (int j = 0; j < 8; ++j)
            mma16816(acc[j], a, &bf[j >> 1][(j & 1) * 2]);
    }

    const int gid = lane >> 2, tid2 = lane & 3;
    int rl = warp * 16 + gid;
    int m_lo = m0 + rl, m_hi = m_lo + 8;
    float zl = zv[rl], zh = zv[rl + 8];
    #pragma unroll
    for (int j = 0; j < 8; ++j) {
        int c = h * 64 + j * 8 + tid2 * 2;
        *(unsigned*)&g_O16[(size_t)m_lo * CC + c] = packbf2(acc[j][0] * zl, acc[j][1] * zl);
        *(unsigned*)&g_O16[(size_t)m_hi * CC + c] = packbf2(acc[j][2] * zh, acc[j][3] * zh);
    }
}

// ---------------------------------------------------------------------------
__global__ __launch_bounds__(256) void ln_kernel(
    const float* __restrict__ x, const float* __restrict__ gamma,
    const float* __restrict__ beta, float* __restrict__ out)
{
    int row = blockIdx.x;
    int t = threadIdx.x;
    uint2 ou = *(const uint2*)&g_O16[(size_t)row * CC + t * 4];
    float4 xv = *(const float4*)&x[(size_t)row * CC + t * 4];
    float4 r;
    r.x = xv.x + __bfloat162float(__ushort_as_bfloat16((unsigned short)(ou.x & 0xffff)));
    r.y = xv.y + __bfloat162float(__ushort_as_bfloat16((unsigned short)(ou.x >> 16)));
    r.z = xv.z + __bfloat162float(__ushort_as_bfloat16((unsigned short)(ou.y & 0xffff)));
    r.w = xv.w + __bfloat162float(__ushort_as_bfloat16((unsigned short)(ou.y >> 16)));
    float s  = r.x + r.y + r.z + r.w;
    float sq = r.x * r.x + r.y * r.y + r.z * r.z + r.w * r.w;
    #pragma unroll
    for (int off = 16; off; off >>= 1) {
        s  += __shfl_xor_sync(0xffffffffu, s, off);
        sq += __shfl_xor_sync(0xffffffffu, sq, off);
    }
    __shared__ float ss[8], ssq[8];
    __shared__ float mean_s, rstd_s;
    int w = t >> 5, lane = t & 31;
    if (lane == 0) { ss[w] = s; ssq[w] = sq; }
    __syncthreads();
    if (t == 0) {
        float S = 0.f, SQ = 0.f;
        #pragma unroll
        for (int i = 0; i < 8; i++) { S += ss[i]; SQ += ssq[i]; }
        float mean = S * (1.f / (float)CC);
        float var  = SQ * (1.f / (float)CC) - mean * mean;
        mean_s = mean;
        rstd_s = rsqrtf(var + 1e-12f);
    }
    __syncthreads();
    float mean = mean_s, rstd = rstd_s;
    float4 g  = *(const float4*)&gamma[t * 4];
    float4 be = *(const float4*)&beta[t * 4];
    float4 o;
    o.x = (r.x - mean) * rstd * g.x + be.x;
    o.y = (r.y - mean) * rstd * g.y + be.y;
    o.z = (r.z - mean) * rstd * g.z + be.z;
    o.w = (r.w - mean) * rstd * g.w + be.w;
    *(float4*)&out[(size_t)row * CC + t * 4] = o;
}

// ---------------------------------------------------------------------------
extern "C" void kernel_launch(void* const* d_in, const int* in_sizes, int n_in,
                              void* d_out, int out_size) {
    const float* x     = (const float*)d_in[0];
    const float* Wq    = (const float*)d_in[1];
    const float* bq    = (const float*)d_in[2];
    const float* Wk    = (const float*)d_in[3];
    const float* bk    = (const float*)d_in[4];
    const float* Wv    = (const float*)d_in[5];
    const float* bv    = (const float*)d_in[6];
    const float* gamma = (const float*)d_in[7];
    const float* beta  = (const float*)d_in[8];
    float* out = (float*)d_out;

    init_invfreq_kernel<<<1, 512>>>();
    init_rope_kernel<<<NN, 512>>>();
    conv_all_kernel<<<CONV_BLOCKS, 256>>>(x, Wq, Wk, Wv);

    cudaFuncSetAttribute(gemm_mma_kernel,
                         cudaFuncAttributeMaxDynamicSharedMemorySize, GEMM_SMEM);
    dim3 ggrid(CC / 128, MM / 128, 3);
    gemm_mma_kernel<<<ggrid, 256, GEMM_SMEM>>>(bq, bk, bv);

    kmean_kernel<<<BB, 256>>>();
    cudaFuncSetAttribute(kv_mma_kernel,
                         cudaFuncAttributeMaxDynamicSharedMemorySize, KV_SMEM);
    kv_mma_kernel<<<128, 256, KV_SMEM>>>();
    out_mma_kernel<<<dim3(128, NN / 128), 256>>>();
    ln_kernel<<<MM, 256>>>(x, gamma, beta, out);
}